// round 15
// baseline (speedup 1.0000x reference)
#include <cuda_runtime.h>
#include <cuda_fp16.h>
#include <cstdint>

// Problem constants
#define BB 8
#define SS 1024
#define IN_F 128
#define EE 512
#define HH 8
#define HD 64
#define FF_DIM 2048
#define NL 4
#define ROWS (BB*SS)          // 8192
#define EPS 1e-5f

// ---------------- scratch (device globals; no allocations allowed) ----------
__device__ __align__(16) float g_x[ROWS*EE];                   // fp32 residual stream
__device__ __align__(16) __half g_dbias[(size_t)BB*SS*SS];     // 16 MB fp16 dist bias
__device__ __align__(16) float g_attn[ROWS*EE];                // 16 MB fp32 delta
__device__ __align__(16) float g_part[2*64*EE];
__device__ __align__(16) float g_stats[2*EE];
__device__ __align__(16) float g_sinv[BB*HH*SS];               // 1/sumexp per (b,h,q)
__device__ __align__(16) float g_rpart[8*ROWS];                // per-ktile partial rowsums
// fp16 operand buffers
__device__ __align__(16) __half g_srch[ROWS*IN_F],  g_srcl[ROWS*IN_F];
__device__ __align__(16) __half g_xh[ROWS*EE];
__device__ __align__(16) __half g_qkh[ROWS*1024];
__device__ __align__(16) __half g_wh[(size_t)BB*SS*SS];        // unnormalized w~ fp16
__device__ __align__(16) __half g_ffh[ROWS*FF_DIM];
__device__ __align__(16) __half g_pwh[EE*IN_F],     g_pwl[EE*IN_F];
__device__ __align__(16) __half g_iph[1024*EE];
__device__ __align__(16) __half g_l1h[FF_DIM*EE];
__device__ __align__(16) __half g_l2h[EE*FF_DIM];

// ====================== helpers =============================================
__device__ __forceinline__ uint32_t smem_u32(const void* p){
    uint32_t a;
    asm("{ .reg .u64 t; cvta.to.shared.u64 t, %1; cvt.u32.u64 %0, t; }"
        : "=r"(a) : "l"(p));
    return a;
}
__device__ __forceinline__ void ldsm4(uint32_t& r0, uint32_t& r1, uint32_t& r2, uint32_t& r3,
                                      uint32_t addr){
    asm volatile("ldmatrix.sync.aligned.m8n8.x4.shared.b16 {%0,%1,%2,%3}, [%4];"
                 : "=r"(r0), "=r"(r1), "=r"(r2), "=r"(r3) : "r"(addr));
}
__device__ __forceinline__ void ldsm4t(uint32_t& r0, uint32_t& r1, uint32_t& r2, uint32_t& r3,
                                       uint32_t addr){
    asm volatile("ldmatrix.sync.aligned.m8n8.x4.trans.shared.b16 {%0,%1,%2,%3}, [%4];"
                 : "=r"(r0), "=r"(r1), "=r"(r2), "=r"(r3) : "r"(addr));
}
__device__ __forceinline__ void mma16816(float* c, const uint32_t* a, const uint32_t* b){
    asm volatile("mma.sync.aligned.m16n8k16.row.col.f32.f16.f16.f32 "
                 "{%0,%1,%2,%3}, {%4,%5,%6,%7}, {%8,%9}, {%0,%1,%2,%3};"
                 : "+f"(c[0]), "+f"(c[1]), "+f"(c[2]), "+f"(c[3])
                 : "r"(a[0]), "r"(a[1]), "r"(a[2]), "r"(a[3]), "r"(b[0]), "r"(b[1]));
}
__device__ __forceinline__ void mma16816h(uint32_t* c, const uint32_t* a, const uint32_t* b){
    asm volatile("mma.sync.aligned.m16n8k16.row.col.f16.f16.f16.f16 "
                 "{%0,%1}, {%2,%3,%4,%5}, {%6,%7}, {%0,%1};"
                 : "+r"(c[0]), "+r"(c[1])
                 : "r"(a[0]), "r"(a[1]), "r"(a[2]), "r"(a[3]), "r"(b[0]), "r"(b[1]));
}
#define CP16(d,s)   asm volatile("cp.async.cg.shared.global [%0], [%1], 16;" :: "r"(d), "l"(s) : "memory")
#define CPCOMMIT()  asm volatile("cp.async.commit_group;" ::: "memory")
#define CPWAIT1()   asm volatile("cp.async.wait_group 1;" ::: "memory")

__device__ __forceinline__ float wrsum(float v){
    #pragma unroll
    for (int o = 16; o; o >>= 1) v += __shfl_xor_sync(0xffffffffu, v, o);
    return v;
}
__device__ __forceinline__ float wrmax(float v){
    #pragma unroll
    for (int o = 16; o; o >>= 1) v = fmaxf(v, __shfl_xor_sync(0xffffffffu, v, o));
    return v;
}

// ====================== BK=32 split GEMM (input projection only) ============
#define GEMM_SMEM (3*32768)

__global__ __launch_bounds__(256,2) void gemm_proj(
    const __half* __restrict__ Ah, const __half* __restrict__ Al,
    const __half* __restrict__ Bh, const __half* __restrict__ Bl,
    const float* __restrict__ bias, float* __restrict__ Cf,
    int K, int lda, int ldb, int ldc)
{
    extern __shared__ char sm[];
    int tid = threadIdx.x, lane = tid & 31, wid = tid >> 5;
    int m0 = blockIdx.y * 128, n0 = blockIdx.x * 128;
    int wm0 = (wid >> 2) * 64, wn0 = (wid & 3) * 32;

    float acc[4][4][4];
    #pragma unroll
    for (int i = 0; i < 4; i++)
        #pragma unroll
        for (int j = 0; j < 4; j++)
            #pragma unroll
            for (int e = 0; e < 4; e++) acc[i][j][e] = 0.f;

    uint32_t smBase = smem_u32(sm);
    int nch = K >> 5;

    auto stage = [&](int c, int s){
        uint32_t bs = smBase + s * 32768;
        int k0 = c * 32;
        #pragma unroll
        for (int j = 0; j < 2; j++) {
            int id = tid + j * 256;
            int r = id >> 2, cc = id & 3;
            uint32_t d = bs + (uint32_t)(r * 64 + ((cc ^ ((r >> 1) & 3)) << 4));
            CP16(d, Ah + (long long)(m0 + r) * lda + k0 + cc * 8);
            CP16(d + 8192, Al + (long long)(m0 + r) * lda + k0 + cc * 8);
            uint32_t db = bs + 16384 + (uint32_t)(r * 64 + ((cc ^ ((r >> 1) & 3)) << 4));
            CP16(db, Bh + (long long)(n0 + r) * ldb + k0 + cc * 8);
            CP16(db + 8192, Bl + (long long)(n0 + r) * ldb + k0 + cc * 8);
        }
        CPCOMMIT();
    };
    stage(0, 0);
    if (nch > 1) stage(1, 1); else CPCOMMIT();

    uint32_t aRowB = (uint32_t)(wm0 + (lane & 15)) * 64;
    uint32_t aXor  = ((uint32_t)(lane & 15) >> 1) & 3;
    uint32_t aG    = (uint32_t)(lane >> 4);
    uint32_t bRowB = (uint32_t)(wn0 + ((lane >> 4) << 3) + (lane & 7)) * 64;
    uint32_t bXor  = (((uint32_t)lane & 7) >> 1) & 3;
    uint32_t bG    = (uint32_t)((lane >> 3) & 1);

    for (int c = 0; c < nch; c++) {
        CPWAIT1();
        __syncthreads();
        uint32_t base = smBase + (uint32_t)((c % 3) * 32768);
        #pragma unroll
        for (int ks = 0; ks < 2; ks++) {
            uint32_t bh[8], bl[8];
            #pragma unroll
            for (int ntp = 0; ntp < 2; ntp++) {
                uint32_t ga = (uint32_t)(ks * 2) + bG;
                uint32_t off = bRowB + (uint32_t)(ntp * 1024) + ((ga ^ bXor) << 4);
                ldsm4(bh[ntp*4+0], bh[ntp*4+1], bh[ntp*4+2], bh[ntp*4+3], base + 16384 + off);
                ldsm4(bl[ntp*4+0], bl[ntp*4+1], bl[ntp*4+2], bl[ntp*4+3], base + 24576 + off);
            }
            #pragma unroll
            for (int mt = 0; mt < 4; mt++) {
                uint32_t ga = (uint32_t)(ks * 2) + aG;
                uint32_t off = aRowB + (uint32_t)(mt * 1024) + ((ga ^ aXor) << 4);
                uint32_t ah[4], al[4];
                ldsm4(ah[0], ah[1], ah[2], ah[3], base + off);
                ldsm4(al[0], al[1], al[2], al[3], base + 8192 + off);
                #pragma unroll
                for (int nt = 0; nt < 4; nt++) {
                    const uint32_t* ph = &bh[(nt >> 1) * 4 + (nt & 1) * 2];
                    const uint32_t* pl = &bl[(nt >> 1) * 4 + (nt & 1) * 2];
                    mma16816(acc[mt][nt], ah, ph);
                    mma16816(acc[mt][nt], ah, pl);
                    mma16816(acc[mt][nt], al, ph);
                }
            }
        }
        if (c + 2 < nch) stage(c + 2, (c + 2) % 3); else CPCOMMIT();
    }
    #pragma unroll
    for (int nt = 0; nt < 4; nt++) {
        int cc = n0 + wn0 + nt * 8 + (lane & 3) * 2;
        float b0 = bias[cc], b1 = bias[cc + 1];
        #pragma unroll
        for (int mt = 0; mt < 4; mt++) {
            int r = m0 + wm0 + mt * 16 + (lane >> 2);
            *(float2*)(Cf + (long long)r * ldc + cc) =
                make_float2(acc[mt][nt][0] + b0, acc[mt][nt][1] + b1);
            *(float2*)(Cf + (long long)(r + 8) * ldc + cc) =
                make_float2(acc[mt][nt][2] + b0, acc[mt][nt][3] + b1);
        }
    }
}

// ====================== BK=64 grid-mapped GEMM (w@x, ff2) ===================
// BTRANS: B [K,N] (NN, trans); else [N,K] (NT). OUT: 0 fp32, 2 fp16.
// rpart (optional): 8 per-ktile partial rowsums; epilogue divides by their sum.
#define G64_SMEM (3*32768)

template<bool BTRANS, int OUT, bool RELU>
__global__ __launch_bounds__(256,2) void gemm64(
    const __half* __restrict__ Ah_, const __half* __restrict__ Bh_,
    const float* __restrict__ bias, const float* __restrict__ rpart,
    float* __restrict__ Cf, __half* __restrict__ Ch,
    int K, int lda, int ldb, int ldc,
    long long sA, long long sB, long long sC)
{
    extern __shared__ char sm[];
    int tid = threadIdx.x, lane = tid & 31, wid = tid >> 5;
    int z = blockIdx.z;
    const __half* Ah = Ah_ + (long long)z * sA;
    const __half* Bh = Bh_ + (long long)z * sB;
    int m0 = blockIdx.y * 128, n0 = blockIdx.x * 128;
    int wm0 = (wid >> 2) * 64, wn0 = (wid & 3) * 32;

    float acc[4][4][4];
    #pragma unroll
    for (int i = 0; i < 4; i++)
        #pragma unroll
        for (int j = 0; j < 4; j++)
            #pragma unroll
            for (int e = 0; e < 4; e++) acc[i][j][e] = 0.f;

    uint32_t smBase = smem_u32(sm);
    int nch = K >> 6;

    auto stage = [&](int c, int s){
        uint32_t bs = smBase + s * 32768;
        int k0 = c * 64;
        #pragma unroll
        for (int j = 0; j < 4; j++) {
            int id = tid + j * 256;
            int r = id >> 3, cc = id & 7;
            uint32_t off = (uint32_t)(r * 128 + ((cc ^ (r & 7)) << 4));
            CP16(bs + off, Ah + (long long)(m0 + r) * lda + k0 + cc * 8);
        }
        if (!BTRANS) {
            #pragma unroll
            for (int j = 0; j < 4; j++) {
                int id = tid + j * 256;
                int r = id >> 3, cc = id & 7;
                uint32_t off = (uint32_t)(r * 128 + ((cc ^ (r & 7)) << 4));
                CP16(bs + 16384 + off, Bh + (long long)(n0 + r) * ldb + k0 + cc * 8);
            }
        } else {
            #pragma unroll
            for (int j = 0; j < 4; j++) {
                int id = tid + j * 256;
                int k = id >> 4, cc = id & 15;
                uint32_t off = (uint32_t)(k * 256 + ((cc ^ (k & 7)) << 4));
                CP16(bs + 16384 + off, Bh + (long long)(k0 + k) * ldb + n0 + cc * 8);
            }
        }
        CPCOMMIT();
    };
    stage(0, 0);
    if (nch > 1) stage(1, 1); else CPCOMMIT();

    uint32_t aRow = (uint32_t)(wm0 + (lane & 15));
    uint32_t bRowNT = (uint32_t)(wn0 + ((lane >> 4) << 3) + (lane & 7));
    uint32_t btRow = ((((uint32_t)lane >> 3) & 1) * 8 + ((uint32_t)lane & 7)) * 256;
    uint32_t btNc  = ((uint32_t)wn0 >> 3) + ((uint32_t)lane >> 4);
    uint32_t btXk  = (uint32_t)lane & 7;

    for (int c = 0; c < nch; c++) {
        CPWAIT1();
        __syncthreads();
        uint32_t base = smBase + (uint32_t)((c % 3) * 32768);
        #pragma unroll
        for (int ks = 0; ks < 4; ks++) {
            uint32_t bh[8];
            if (!BTRANS) {
                #pragma unroll
                for (int ntp = 0; ntp < 2; ntp++) {
                    uint32_t row = bRowNT + (uint32_t)(ntp * 16);
                    uint32_t g = (uint32_t)(ks * 2) + (uint32_t)((lane >> 3) & 1);
                    uint32_t off = row * 128 + ((g ^ (row & 7)) << 4);
                    ldsm4(bh[ntp*4+0], bh[ntp*4+1], bh[ntp*4+2], bh[ntp*4+3],
                          base + 16384 + off);
                }
            } else {
                #pragma unroll
                for (int ntp = 0; ntp < 2; ntp++) {
                    uint32_t off = btRow + (uint32_t)(ks * 4096)
                                 + (((btNc + (uint32_t)(ntp * 2)) ^ btXk) << 4);
                    ldsm4t(bh[ntp*4+0], bh[ntp*4+1], bh[ntp*4+2], bh[ntp*4+3],
                           base + 16384 + off);
                }
            }
            #pragma unroll
            for (int mt = 0; mt < 4; mt++) {
                uint32_t row = aRow + (uint32_t)(mt * 16);
                uint32_t g = (uint32_t)(ks * 2) + (uint32_t)(lane >> 4);
                uint32_t off = row * 128 + ((g ^ (row & 7)) << 4);
                uint32_t ah[4];
                ldsm4(ah[0], ah[1], ah[2], ah[3], base + off);
                #pragma unroll
                for (int nt = 0; nt < 4; nt++)
                    mma16816(acc[mt][nt], ah, &bh[(nt >> 1) * 4 + (nt & 1) * 2]);
            }
        }
        if (c + 2 < nch) stage(c + 2, (c + 2) % 3); else CPCOMMIT();
    }

    float rd0[4], rd1[4];
    if (rpart) {
        #pragma unroll
        for (int mt = 0; mt < 4; mt++) {
            int r = m0 + wm0 + mt * 16 + (lane >> 2);
            long long rb = (long long)z * 1024 + r;
            float s0 = 0.f, s1 = 0.f;
            #pragma unroll
            for (int kt = 0; kt < 8; kt++) {
                s0 += rpart[kt * ROWS + rb];
                s1 += rpart[kt * ROWS + rb + 8];
            }
            rd0[mt] = 1.f / s0;
            rd1[mt] = 1.f / s1;
        }
    }

    #pragma unroll
    for (int nt = 0; nt < 4; nt++) {
        int cc = n0 + wn0 + nt * 8 + (lane & 3) * 2;
        float b0 = 0.f, b1 = 0.f;
        if (bias) { b0 = bias[cc]; b1 = bias[cc + 1]; }
        #pragma unroll
        for (int mt = 0; mt < 4; mt++) {
            int r = m0 + wm0 + mt * 16 + (lane >> 2);
            float v0 = acc[mt][nt][0] + b0;
            float v1 = acc[mt][nt][1] + b1;
            float v2 = acc[mt][nt][2] + b0;
            float v3 = acc[mt][nt][3] + b1;
            if (rpart) { v0 *= rd0[mt]; v1 *= rd0[mt]; v2 *= rd1[mt]; v3 *= rd1[mt]; }
            if (RELU) { v0 = fmaxf(v0,0.f); v1 = fmaxf(v1,0.f); v2 = fmaxf(v2,0.f); v3 = fmaxf(v3,0.f); }
            if (OUT == 0) {
                float* p = Cf + (long long)z * sC;
                *(float2*)(p + (long long)r * ldc + cc)       = make_float2(v0, v1);
                *(float2*)(p + (long long)(r + 8) * ldc + cc) = make_float2(v2, v3);
            } else {
                __half* ph = Ch + (long long)z * sC;
                *(__half2*)(ph + (long long)r * ldc + cc) =
                    __halves2half2(__float2half_rn(v0), __float2half_rn(v1));
                *(__half2*)(ph + (long long)(r + 8) * ldc + cc) =
                    __halves2half2(__float2half_rn(v2), __float2half_rn(v3));
            }
        }
    }
}

// ====================== persistent continuous-pipeline GEMM (NT, fp16 out) ==
// Tile stream per CTA: t = bid + i*G; flat j over (tile, chunk). The cp.async
// ring never drains across tile boundaries; epilogue is register-only.
template<bool RELU>
__global__ __launch_bounds__(256,2) void gemm64p(
    const __half* __restrict__ Ah, const __half* __restrict__ Bh,
    const float* __restrict__ bias, __half* __restrict__ Ch,
    int K, int lda, int ldb, int ldc, int nx, int nTiles)
{
    extern __shared__ char sm[];
    int tid = threadIdx.x, lane = tid & 31, wid = tid >> 5;
    int wm0 = (wid >> 2) * 64, wn0 = (wid & 3) * 32;
    uint32_t smBase = smem_u32(sm);
    int nch = K >> 6;
    int G = gridDim.x, bid = blockIdx.x;
    if (bid >= nTiles) return;
    int nloc = (nTiles - 1 - bid) / G + 1;
    int totalJ = nloc * nch;

    auto stage = [&](int j, int s){
        int i = j / nch, c = j % nch;
        int t = bid + i * G;
        int m0 = (t / nx) * 128, n0 = (t % nx) * 128;
        uint32_t bs = smBase + s * 32768;
        int k0 = c * 64;
        #pragma unroll
        for (int j4 = 0; j4 < 4; j4++) {
            int id = tid + j4 * 256;
            int r = id >> 3, cc = id & 7;
            uint32_t off = (uint32_t)(r * 128 + ((cc ^ (r & 7)) << 4));
            CP16(bs + off,         Ah + (long long)(m0 + r) * lda + k0 + cc * 8);
            CP16(bs + 16384 + off, Bh + (long long)(n0 + r) * ldb + k0 + cc * 8);
        }
        CPCOMMIT();
    };
    stage(0, 0);
    if (totalJ > 1) stage(1, 1); else CPCOMMIT();

    float acc[4][4][4];
    #pragma unroll
    for (int i = 0; i < 4; i++)
        #pragma unroll
        for (int j = 0; j < 4; j++)
            #pragma unroll
            for (int e = 0; e < 4; e++) acc[i][j][e] = 0.f;

    uint32_t aRow = (uint32_t)(wm0 + (lane & 15));
    uint32_t bRowNT = (uint32_t)(wn0 + ((lane >> 4) << 3) + (lane & 7));

    for (int j = 0; j < totalJ; j++) {
        CPWAIT1();
        __syncthreads();
        uint32_t base = smBase + (uint32_t)((j % 3) * 32768);
        #pragma unroll
        for (int ks = 0; ks < 4; ks++) {
            uint32_t bh[8];
            #pragma unroll
            for (int ntp = 0; ntp < 2; ntp++) {
                uint32_t row = bRowNT + (uint32_t)(ntp * 16);
                uint32_t g = (uint32_t)(ks * 2) + (uint32_t)((lane >> 3) & 1);
                uint32_t off = row * 128 + ((g ^ (row & 7)) << 4);
                ldsm4(bh[ntp*4+0], bh[ntp*4+1], bh[ntp*4+2], bh[ntp*4+3],
                      base + 16384 + off);
            }
            #pragma unroll
            for (int mt = 0; mt < 4; mt++) {
                uint32_t row = aRow + (uint32_t)(mt * 16);
                uint32_t g = (uint32_t)(ks * 2) + (uint32_t)(lane >> 4);
                uint32_t off = row * 128 + ((g ^ (row & 7)) << 4);
                uint32_t ah[4];
                ldsm4(ah[0], ah[1], ah[2], ah[3], base + off);
                #pragma unroll
                for (int nt = 0; nt < 4; nt++)
                    mma16816(acc[mt][nt], ah, &bh[(nt >> 1) * 4 + (nt & 1) * 2]);
            }
        }
        if (j + 2 < totalJ) stage(j + 2, (j + 2) % 3); else CPCOMMIT();
        if ((j % nch) == nch - 1) {
            // tile epilogue (registers only; overlaps in-flight next-tile loads)
            int t = bid + (j / nch) * G;
            int m0 = (t / nx) * 128, n0 = (t % nx) * 128;
            #pragma unroll
            for (int nt = 0; nt < 4; nt++) {
                int cc = n0 + wn0 + nt * 8 + (lane & 3) * 2;
                float b0 = bias[cc], b1 = bias[cc + 1];
                #pragma unroll
                for (int mt = 0; mt < 4; mt++) {
                    int r = m0 + wm0 + mt * 16 + (lane >> 2);
                    float v0 = acc[mt][nt][0] + b0;
                    float v1 = acc[mt][nt][1] + b1;
                    float v2 = acc[mt][nt][2] + b0;
                    float v3 = acc[mt][nt][3] + b1;
                    if (RELU) { v0=fmaxf(v0,0.f); v1=fmaxf(v1,0.f); v2=fmaxf(v2,0.f); v3=fmaxf(v3,0.f); }
                    *(__half2*)(Ch + (long long)r * ldc + cc) =
                        __halves2half2(__float2half_rn(v0), __float2half_rn(v1));
                    *(__half2*)(Ch + (long long)(r + 8) * ldc + cc) =
                        __halves2half2(__float2half_rn(v2), __float2half_rn(v3));
                    acc[mt][nt][0] = 0.f; acc[mt][nt][1] = 0.f;
                    acc[mt][nt][2] = 0.f; acc[mt][nt][3] = 0.f;
                }
            }
        }
    }
}

// ====================== fused attention pass A: 1/sumexp ====================
#define SE_SMEM (3*16384)

__global__ __launch_bounds__(256,2) void sumexp_k(
    const __half* __restrict__ qk, float* __restrict__ sinv)
{
    extern __shared__ char sm[];
    int tid = threadIdx.x, lane = tid & 31, wid = tid >> 5;
    int wm0 = wid * 16;
    int z = blockIdx.y, b = z >> 3, h = z & 7;
    int m0 = blockIdx.x * 128;
    const __half* qb = qk + (long long)b * SS * 1024 + h * 64;
    const __half* kb = qb + 512;
    uint32_t smBase = smem_u32(sm);

    #pragma unroll
    for (int j = 0; j < 4; j++) {
        int id = tid + j * 256;
        int r = id >> 3, cc = id & 7;
        uint32_t off = (uint32_t)(r * 128 + ((cc ^ (r & 7)) << 4));
        CP16(smBase + off, qb + (long long)(m0 + r) * 1024 + cc * 8);
    }
    auto stageK = [&](int kt, int s){
        uint32_t bs = smBase + 16384 + s * 16384;
        int n0 = kt * 128;
        #pragma unroll
        for (int j = 0; j < 4; j++) {
            int id = tid + j * 256;
            int r = id >> 3, cc = id & 7;
            uint32_t off = (uint32_t)(r * 128 + ((cc ^ (r & 7)) << 4));
            CP16(bs + off, kb + (long long)(n0 + r) * 1024 + cc * 8);
        }
        CPCOMMIT();
    };
    stageK(0, 0);
    stageK(1, 1);

    uint32_t aRow = (uint32_t)(wm0 + (lane & 15));
    uint32_t bRow0 = (uint32_t)(((lane >> 4) << 3) + (lane & 7));
    float sum0 = 0.f, sum1 = 0.f;

    for (int kt = 0; kt < 8; kt++) {
        CPWAIT1();
        __syncthreads();
        uint32_t kbase = smBase + 16384 + (uint32_t)((kt & 1) * 16384);
        uint32_t hacc[16][2];
        #pragma unroll
        for (int i = 0; i < 16; i++) { hacc[i][0] = 0u; hacc[i][1] = 0u; }
        #pragma unroll
        for (int ks = 0; ks < 4; ks++) {
            uint32_t ag = (uint32_t)(ks * 2) + (uint32_t)(lane >> 4);
            uint32_t ah[4];
            ldsm4(ah[0], ah[1], ah[2], ah[3],
                  smBase + aRow * 128 + ((ag ^ (aRow & 7)) << 4));
            #pragma unroll
            for (int ntp = 0; ntp < 8; ntp++) {
                uint32_t row = bRow0 + (uint32_t)(ntp * 16);
                uint32_t bg = (uint32_t)(ks * 2) + (uint32_t)((lane >> 3) & 1);
                uint32_t r4[4];
                ldsm4(r4[0], r4[1], r4[2], r4[3],
                      kbase + row * 128 + ((bg ^ (row & 7)) << 4));
                mma16816h(hacc[ntp*2],     ah, &r4[0]);
                mma16816h(hacc[ntp*2 + 1], ah, &r4[2]);
            }
        }
        #pragma unroll
        for (int nt = 0; nt < 16; nt++) {
            float2 f0 = __half22float2(*reinterpret_cast<__half2*>(&hacc[nt][0]));
            float2 f1 = __half22float2(*reinterpret_cast<__half2*>(&hacc[nt][1]));
            sum0 += __expf(f0.x * 0.125f) + __expf(f0.y * 0.125f);
            sum1 += __expf(f1.x * 0.125f) + __expf(f1.y * 0.125f);
        }
        __syncthreads();
        if (kt + 2 < 8) stageK(kt + 2, kt & 1); else CPCOMMIT();
    }
    sum0 += __shfl_xor_sync(0xffffffffu, sum0, 1);
    sum0 += __shfl_xor_sync(0xffffffffu, sum0, 2);
    sum1 += __shfl_xor_sync(0xffffffffu, sum1, 1);
    sum1 += __shfl_xor_sync(0xffffffffu, sum1, 2);
    if ((lane & 3) == 0) {
        int r = m0 + wm0 + (lane >> 2);
        sinv[(long long)z * SS + r]     = 1.f / sum0;
        sinv[(long long)z * SS + r + 8] = 1.f / sum1;
    }
}

// ====================== fused attention pass B: w~ + partial rowsums ========
#define FW_SMEM (2*32768)

__global__ __launch_bounds__(256,2) void fuse_w_k(
    const __half* __restrict__ qk, const float* __restrict__ sinv,
    const __half* __restrict__ dbias, __half* __restrict__ wh,
    float* __restrict__ rpart)
{
    extern __shared__ char sm[];
    int tid = threadIdx.x, lane = tid & 31, wid = tid >> 5;
    int wm0 = wid * 16;
    int b = blockIdx.z, qt = blockIdx.y, kt = blockIdx.x;
    int m0 = qt * 128, n0 = kt * 128;
    const __half* base_q = qk + (long long)b * SS * 1024;
    uint32_t smBase = smem_u32(sm);

    auto stageH = [&](int h, int s){
        uint32_t bs = smBase + s * 32768;
        const __half* qb = base_q + h * 64;
        const __half* kb = qb + 512;
        #pragma unroll
        for (int j = 0; j < 8; j++) {
            int id = tid + j * 256;
            int r = (id & 1023) >> 3, cc = id & 7;
            uint32_t off = (uint32_t)(r * 128 + ((cc ^ (r & 7)) << 4));
            if (id < 1024) CP16(bs + off, qb + (long long)(m0 + r) * 1024 + cc * 8);
            else           CP16(bs + 16384 + off, kb + (long long)(n0 + r) * 1024 + cc * 8);
        }
        CPCOMMIT();
    };
    stageH(0, 0);
    stageH(1, 1);

    uint32_t aRow = (uint32_t)(wm0 + (lane & 15));
    uint32_t bRow0 = (uint32_t)(((lane >> 4) << 3) + (lane & 7));
    int r0 = wm0 + (lane >> 2);
    uint32_t wacc[16][2];
    #pragma unroll
    for (int i = 0; i < 16; i++) { wacc[i][0] = 0u; wacc[i][1] = 0u; }

    for (int h = 0; h < 8; h++) {
        CPWAIT1();
        __syncthreads();
        uint32_t qbase = smBase + (uint32_t)((h & 1) * 32768);
        uint32_t kbase = qbase + 16384;
        uint32_t hacc[16][2];
        #pragma unroll
        for (int i = 0; i < 16; i++) { hacc[i][0] = 0u; hacc[i][1] = 0u; }
        #pragma unroll
        for (int ks = 0; ks < 4; ks++) {
            uint32_t ag = (uint32_t)(ks * 2) + (uint32_t)(lane >> 4);
            uint32_t ah[4];
            ldsm4(ah[0], ah[1], ah[2], ah[3],
                  qbase + aRow * 128 + ((ag ^ (aRow & 7)) << 4));
            #pragma unroll
            for (int ntp = 0; ntp < 8; ntp++) {
                uint32_t row = bRow0 + (uint32_t)(ntp * 16);
                uint32_t bg = (uint32_t)(ks * 2) + (uint32_t)((lane >> 3) & 1);
                uint32_t r4[4];
                ldsm4(r4[0], r4[1], r4[2], r4[3],
                      kbase + row * 128 + ((bg ^ (row & 7)) << 4));
                mma16816h(hacc[ntp*2],     ah, &r4[0]);
                mma16816h(hacc[ntp*2 + 1], ah, &r4[2]);
            }
        }
        long long sbase = (long long)(b * 8 + h) * SS + m0;
        float is0 = sinv[sbase + r0];
        float is1 = sinv[sbase + r0 + 8];
        #pragma unroll
        for (int nt = 0; nt < 16; nt++) {
            float2 f0 = __half22float2(*reinterpret_cast<__half2*>(&hacc[nt][0]));
            float2 f1 = __half22float2(*reinterpret_cast<__half2*>(&hacc[nt][1]));
            __half2 t0 = __floats2half2_rn(__expf(f0.x * 0.125f) * is0,
                                           __expf(f0.y * 0.125f) * is0);
            __half2 t1 = __floats2half2_rn(__expf(f1.x * 0.125f) * is1,
                                           __expf(f1.y * 0.125f) * is1);
            *reinterpret_cast<__half2*>(&wacc[nt][0]) =
                __hadd2(*reinterpret_cast<__half2*>(&wacc[nt][0]), t0);
            *reinterpret_cast<__half2*>(&wacc[nt][1]) =
                __hadd2(*reinterpret_cast<__half2*>(&wacc[nt][1]), t1);
        }
        __syncthreads();
        if (h + 2 < 8) stageH(h + 2, h & 1); else CPCOMMIT();
    }

    // multiply by dist bias, store w~, and emit per-ktile partial rowsums
    long long row0 = (long long)(b * SS + m0 + r0);
    const __half* db0 = dbias + row0 * SS;
    __half* wp0 = wh + row0 * SS;
    int ccb = n0 + (lane & 3) * 2;
    float ps0 = 0.f, ps1 = 0.f;
    #pragma unroll
    for (int nt = 0; nt < 16; nt++) {
        int col = ccb + nt * 8;
        __half2 d0 = *(const __half2*)(db0 + col);
        __half2 d1 = *(const __half2*)(db0 + 8 * SS + col);
        __half2 v0 = __hmul2(*reinterpret_cast<__half2*>(&wacc[nt][0]), d0);
        __half2 v1 = __hmul2(*reinterpret_cast<__half2*>(&wacc[nt][1]), d1);
        *(__half2*)(wp0 + col) = v0;
        *(__half2*)(wp0 + 8 * SS + col) = v1;
        float2 f0 = __half22float2(v0), f1 = __half22float2(v1);
        ps0 += f0.x + f0.y;
        ps1 += f1.x + f1.y;
    }
    ps0 += __shfl_xor_sync(0xffffffffu, ps0, 1);
    ps0 += __shfl_xor_sync(0xffffffffu, ps0, 2);
    ps1 += __shfl_xor_sync(0xffffffffu, ps1, 1);
    ps1 += __shfl_xor_sync(0xffffffffu, ps1, 2);
    if ((lane & 3) == 0) {
        rpart[kt * ROWS + row0]     = ps0;
        rpart[kt * ROWS + row0 + 8] = ps1;
    }
}

// ---------------- fp32 -> fp16 converters (8 elems/thread) ------------------
__global__ void split_k(const float* __restrict__ in, __half* __restrict__ h,
                        __half* __restrict__ l, int n8) {
    int i = blockIdx.x * 256 + threadIdx.x;
    if (i >= n8) return;
    long long base = (long long)i * 8;
    float4 a = *(const float4*)(in + base);
    float4 b = *(const float4*)(in + base + 4);
    float va[8] = {a.x, a.y, a.z, a.w, b.x, b.y, b.z, b.w};
    uint4 hp, lp;
    uint32_t* hw = reinterpret_cast<uint32_t*>(&hp);
    uint32_t* lw = reinterpret_cast<uint32_t*>(&lp);
    #pragma unroll
    for (int j = 0; j < 4; j++) {
        __half h0 = __float2half_rn(va[j*2]), h1 = __float2half_rn(va[j*2+1]);
        __half2 hh = __halves2half2(h0, h1);
        __half2 ll = __halves2half2(__float2half_rn(va[j*2]   - __half2float(h0)),
                                    __float2half_rn(va[j*2+1] - __half2float(h1)));
        hw[j] = *reinterpret_cast<uint32_t*>(&hh);
        lw[j] = *reinterpret_cast<uint32_t*>(&ll);
    }
    *(uint4*)(h + base) = hp;
    *(uint4*)(l + base) = lp;
}
__global__ void cvt_k(const float* __restrict__ in, __half* __restrict__ h, int n8) {
    int i = blockIdx.x * 256 + threadIdx.x;
    if (i >= n8) return;
    long long base = (long long)i * 8;
    float4 a = *(const float4*)(in + base);
    float4 b = *(const float4*)(in + base + 4);
    uint4 hp;
    uint32_t* hw = reinterpret_cast<uint32_t*>(&hp);
    __half2 h0 = __floats2half2_rn(a.x, a.y);
    __half2 h1 = __floats2half2_rn(a.z, a.w);
    __half2 h2 = __floats2half2_rn(b.x, b.y);
    __half2 h3 = __floats2half2_rn(b.z, b.w);
    hw[0] = *reinterpret_cast<uint32_t*>(&h0);
    hw[1] = *reinterpret_cast<uint32_t*>(&h1);
    hw[2] = *reinterpret_cast<uint32_t*>(&h2);
    hw[3] = *reinterpret_cast<uint32_t*>(&h3);
    *(uint4*)(h + base) = hp;
}

// ---------------- BatchNorm (training-mode batch stats), deterministic -----
__global__ void bn_part_k(const float* __restrict__ x, float* __restrict__ part) {
    int e = threadIdx.x;
    int blk = blockIdx.x;
    float s = 0.f, sq = 0.f;
    int r0 = blk * 128;
    for (int r = r0; r < r0 + 128; r++) {
        float v = x[(long long)r * EE + e];
        s += v; sq += v * v;
    }
    part[blk * EE + e] = s;
    part[(64 + blk) * EE + e] = sq;
}

__global__ void bn_final_k(const float* __restrict__ part, float* __restrict__ stats) {
    int e = blockIdx.x * blockDim.x + threadIdx.x;
    float s = 0.f, sq = 0.f;
    for (int i = 0; i < 64; i++) {
        s  += part[i * EE + e];
        sq += part[(64 + i) * EE + e];
    }
    float mu = s / (float)ROWS;
    stats[e] = mu;
    stats[EE + e] = sq / (float)ROWS - mu * mu;
}

__global__ void bn_apply_pe_k(float* __restrict__ x, const float* __restrict__ stats,
                              const float* __restrict__ g, const float* __restrict__ b,
                              __half* __restrict__ xh) {
    long long idx = (long long)blockIdx.x * blockDim.x + threadIdx.x;
    int e = (int)(idx & (EE - 1));
    long long r = idx >> 9;
    int s = (int)(r & (SS - 1));
    float mu = stats[e], var = stats[EE + e];
    int j = e >> 1;
    float dt = expf((float)(2 * j) * (-9.210340371976184f / (float)EE));
    float ang = (float)s * dt;
    float pe = (e & 1) ? cosf(ang) : sinf(ang);
    float v = (x[idx] - mu) * rsqrtf(var + EPS) * g[e] + b[e] + pe;
    x[idx] = v;
    xh[idx] = __float2half_rn(v);
}

// ---------------- distance bias (warp per row, fp16 out) --------------------
__global__ void dist_bias_k(const float* __restrict__ d, const float* __restrict__ scale_p,
                            __half* __restrict__ bias) {
    int row = blockIdx.x * 8 + (threadIdx.x >> 5);
    int lane = threadIdx.x & 31;
    const float* dp = d + (long long)row * SS + lane * 4;
    float4 v[8];
    float mx = -1e30f;
    #pragma unroll
    for (int i = 0; i < 8; i++) {
        v[i] = *(const float4*)(dp + i * 128);
        mx = fmaxf(mx, fmaxf(fmaxf(v[i].x, v[i].y), fmaxf(v[i].z, v[i].w)));
    }
    mx = wrmax(mx);
    float inv_dmax = 1.f / mx;
    float sc = scale_p[0];
    __half* bp = bias + (long long)row * SS + lane * 4;
    #pragma unroll
    for (int i = 0; i < 8; i++) {
        __half2 h0 = __halves2half2(__float2half_rn(expf(sc * (1.f - v[i].x * inv_dmax))),
                                    __float2half_rn(expf(sc * (1.f - v[i].y * inv_dmax))));
        __half2 h1 = __halves2half2(__float2half_rn(expf(sc * (1.f - v[i].z * inv_dmax))),
                                    __float2half_rn(expf(sc * (1.f - v[i].w * inv_dmax))));
        uint2 pk; pk.x = *reinterpret_cast<uint32_t*>(&h0); pk.y = *reinterpret_cast<uint32_t*>(&h1);
        *(uint2*)(bp + i * 128) = pk;
    }
}

// ---------------- fused residual + LayerNorm (warp per row) -----------------
template<bool SPLIT>
__global__ void add_ln_k(const float* __restrict__ x, const float* __restrict__ r,
                         const float* __restrict__ g, const float* __restrict__ b,
                         float* __restrict__ out, __half* __restrict__ oh) {
    int row = blockIdx.x * 8 + (threadIdx.x >> 5);
    int lane = threadIdx.x & 31;
    long long base = (long long)row * EE + lane * 4;
    float4 v[4];
    float s = 0.f, sq = 0.f;
    #pragma unroll
    for (int i = 0; i < 4; i++) {
        float4 a = *(const float4*)(x + base + i * 128);
        float4 rr = *(const float4*)(r + base + i * 128);
        a.x += rr.x; a.y += rr.y; a.z += rr.z; a.w += rr.w;
        v[i] = a;
        s += a.x + a.y + a.z + a.w;
        sq += a.x*a.x + a.y*a.y + a.z*a.z + a.w*a.w;
    }
    float mean = wrsum(s) * (1.f / (float)EE);
    float var = wrsum(sq) * (1.f / (float)EE) - mean * mean;
    float inv = rsqrtf(var + EPS);
    #pragma unroll
    for (int i = 0; i < 4; i++) {
        float4 gg = *(const float4*)(g + lane * 4 + i * 128);
        float4 bb = *(const float4*)(b + lane * 4 + i * 128);
        float4 o;
        o.x = (v[i].x - mean) * inv * gg.x + bb.x;
        o.y = (v[i].y - mean) * inv * gg.y + bb.y;
        o.z = (v[i].z - mean) * inv * gg.z + bb.z;
        o.w = (v[i].w - mean) * inv * gg.w + bb.w;
        *(float4*)(out + base + i * 128) = o;
        if (SPLIT) {
            __half2 h0 = __halves2half2(__float2half_rn(o.x), __float2half_rn(o.y));
            __half2 h1 = __halves2half2(__float2half_rn(o.z), __float2half_rn(o.w));
            uint2 pk; pk.x = *reinterpret_cast<uint32_t*>(&h0); pk.y = *reinterpret_cast<uint32_t*>(&h1);
            *(uint2*)(oh + base + i * 128) = pk;
        }
    }
}

// ---------------- launch -----------------------------------------------------
extern "C" void kernel_launch(void* const* d_in, const int* in_sizes, int n_in,
                              void* d_out, int out_size) {
    (void)in_sizes; (void)n_in; (void)out_size;
    const float* src        = (const float*)d_in[0];
    const float* distances  = (const float*)d_in[1];
    const float* proj_w     = (const float*)d_in[2];
    const float* proj_b     = (const float*)d_in[3];
    const float* bn_g       = (const float*)d_in[4];
    const float* bn_b       = (const float*)d_in[5];
    const float* in_proj_w  = (const float*)d_in[6];
    const float* in_proj_b  = (const float*)d_in[7];
    const float* dist_scale = (const float*)d_in[8];
    const float* lin1_w     = (const float*)d_in[9];
    const float* lin1_b     = (const float*)d_in[10];
    const float* lin2_w     = (const float*)d_in[11];
    const float* lin2_b     = (const float*)d_in[12];
    const float* n1_g       = (const float*)d_in[13];
    const float* n1_b       = (const float*)d_in[14];
    const float* n2_g       = (const float*)d_in[15];
    const float* n2_b       = (const float*)d_in[16];
    float* out = (float*)d_out;

    float *x, *attn, *part, *stats, *sinv, *rpart;
    __half *dbias, *srch, *srcl, *xh, *qkh, *wh, *ffh;
    __half *pwh, *pwl, *iph, *l1h, *l2h;
    cudaGetSymbolAddress((void**)&x,     g_x);
    cudaGetSymbolAddress((void**)&dbias, g_dbias);
    cudaGetSymbolAddress((void**)&attn,  g_attn);
    cudaGetSymbolAddress((void**)&part,  g_part);
    cudaGetSymbolAddress((void**)&stats, g_stats);
    cudaGetSymbolAddress((void**)&sinv,  g_sinv);
    cudaGetSymbolAddress((void**)&rpart, g_rpart);
    cudaGetSymbolAddress((void**)&srch,  g_srch); cudaGetSymbolAddress((void**)&srcl, g_srcl);
    cudaGetSymbolAddress((void**)&xh,    g_xh);
    cudaGetSymbolAddress((void**)&qkh,   g_qkh);
    cudaGetSymbolAddress((void**)&wh,    g_wh);
    cudaGetSymbolAddress((void**)&ffh,   g_ffh);
    cudaGetSymbolAddress((void**)&pwh,   g_pwh);  cudaGetSymbolAddress((void**)&pwl,  g_pwl);
    cudaGetSymbolAddress((void**)&iph,   g_iph);
    cudaGetSymbolAddress((void**)&l1h,   g_l1h);
    cudaGetSymbolAddress((void**)&l2h,   g_l2h);

    cudaFuncSetAttribute(gemm_proj, cudaFuncAttributeMaxDynamicSharedMemorySize, GEMM_SMEM);
    cudaFuncSetAttribute(gemm64<true,0,false>,  cudaFuncAttributeMaxDynamicSharedMemorySize, G64_SMEM);
    cudaFuncSetAttribute(gemm64<false,0,false>, cudaFuncAttributeMaxDynamicSharedMemorySize, G64_SMEM);
    cudaFuncSetAttribute(gemm64p<false>, cudaFuncAttributeMaxDynamicSharedMemorySize, G64_SMEM);
    cudaFuncSetAttribute(gemm64p<true>,  cudaFuncAttributeMaxDynamicSharedMemorySize, G64_SMEM);
    cudaFuncSetAttribute(sumexp_k, cudaFuncAttributeMaxDynamicSharedMemorySize, SE_SMEM);
    cudaFuncSetAttribute(fuse_w_k, cudaFuncAttributeMaxDynamicSharedMemorySize, FW_SMEM);

    dim3 blk(256);
    const long long SE  = (long long)SS * EE;
    const long long SS2 = (long long)SS * SS;
    const int PG = 296;   // persistent grid: 2 CTAs/SM x 148

    // 0) one-time conversions
    split_k<<<(ROWS*IN_F/8+255)/256, 256>>>(src, srch, srcl, ROWS*IN_F/8);
    split_k<<<(EE*IN_F/8+255)/256, 256>>>(proj_w, pwh, pwl, EE*IN_F/8);
    cvt_k<<<(1024*EE/8+255)/256, 256>>>(in_proj_w, iph, 1024*EE/8);
    cvt_k<<<(FF_DIM*EE/8+255)/256, 256>>>(lin1_w, l1h, FF_DIM*EE/8);
    cvt_k<<<(EE*FF_DIM/8+255)/256, 256>>>(lin2_w, l2h, EE*FF_DIM/8);

    // 1) input projection -> g_x (fp32), 3-pass
    gemm_proj<<<dim3(EE/128, ROWS/128, 1), blk, GEMM_SMEM>>>(
        srch, srcl, pwh, pwl, proj_b, x, IN_F, IN_F, IN_F, EE);

    // 2) BatchNorm + PE (+fp16 mirror)
    bn_part_k<<<64, 512>>>(x, part);
    bn_final_k<<<2, 256>>>(part, stats);
    bn_apply_pe_k<<<(ROWS*EE)/256, 256>>>(x, stats, bn_g, bn_b, xh);

    // 3) distance bias
    dist_bias_k<<<BB*SS/8, 256>>>(distances, dist_scale, dbias);

    // 4) layers
    for (int l = 0; l < NL; l++) {
        // qk projection -> fp16 (persistent, continuous pipeline; 512 tiles)
        gemm64p<false><<<PG, blk, G64_SMEM>>>(
            xh, iph, in_proj_b, qkh, EE, EE, EE, 1024, 8, 512);

        // fused attention weights (+partial rowsums; no rowinv launch)
        sumexp_k<<<dim3(8, BB*HH), blk, SE_SMEM>>>(qkh, sinv);
        fuse_w_k<<<dim3(8, 8, BB), blk, FW_SMEM>>>(qkh, sinv, dbias, wh, rpart);

        // attn_out = (w~ @ x) / rowsum -> fp32
        gemm64<true,0,false><<<dim3(EE/128, SS/128, BB), blk, G64_SMEM>>>(
            wh, xh, nullptr, rpart, attn, nullptr,
            SS, SS, EE, EE, SS2, SE, SE);

        // x = LN(x + attn_out)
        add_ln_k<true><<<ROWS/8, 256>>>(x, attn, n1_g, n1_b, x, xh);

        // FFN: ff1 persistent (1024 tiles); ff2 grid-mapped
        gemm64p<true><<<PG, blk, G64_SMEM>>>(
            xh, l1h, lin1_b, ffh, EE, EE, EE, FF_DIM, 16, 1024);
        gemm64<false,0,false><<<dim3(EE/128, ROWS/128, 1), blk, G64_SMEM>>>(
            ffh, l2h, lin2_b, nullptr, attn, nullptr,
            FF_DIM, FF_DIM, FF_DIM, EE, 0, 0, 0);

        // x = LN(x + ff); last layer -> d_out
        if (l == NL - 1)
            add_ln_k<false><<<ROWS/8, 256>>>(x, attn, n2_g, n2_b, out, nullptr);
        else
            add_ln_k<true><<<ROWS/8, 256>>>(x, attn, n2_g, n2_b, x, xh);
    }
}

// round 16
// speedup vs baseline: 1.0239x; 1.0239x over previous
#include <cuda_runtime.h>
#include <cuda_fp16.h>
#include <cstdint>

// Problem constants
#define BB 8
#define SS 1024
#define IN_F 128
#define EE 512
#define HH 8
#define HD 64
#define FF_DIM 2048
#define NL 4
#define ROWS (BB*SS)          // 8192
#define EPS 1e-5f

// ---------------- scratch (device globals; no allocations allowed) ----------
__device__ __align__(16) float g_x[ROWS*EE];                   // fp32 residual stream
__device__ __align__(16) __half g_dbias[(size_t)BB*SS*SS];     // 16 MB fp16 dist bias
__device__ __align__(16) float g_attn[ROWS*EE];                // 16 MB fp32 delta
__device__ __align__(16) float g_part[2*64*EE];
__device__ __align__(16) float g_stats[2*EE];
__device__ __align__(16) float g_sinv[BB*HH*SS];               // 1/sumexp per (b,h,q)
__device__ __align__(16) float g_rpart[8*ROWS];                // per-ktile partial rowsums
// fp16 operand buffers
__device__ __align__(16) __half g_srch[ROWS*IN_F],  g_srcl[ROWS*IN_F];
__device__ __align__(16) __half g_xh[ROWS*EE];
__device__ __align__(16) __half g_qkh[ROWS*1024];
__device__ __align__(16) __half g_wh[(size_t)BB*SS*SS];        // unnormalized w~ fp16
__device__ __align__(16) __half g_ffh[ROWS*FF_DIM];
__device__ __align__(16) __half g_pwh[EE*IN_F],     g_pwl[EE*IN_F];
__device__ __align__(16) __half g_iph[1024*EE];
__device__ __align__(16) __half g_l1h[FF_DIM*EE];
__device__ __align__(16) __half g_l2h[EE*FF_DIM];

// ====================== helpers =============================================
__device__ __forceinline__ uint32_t smem_u32(const void* p){
    uint32_t a;
    asm("{ .reg .u64 t; cvta.to.shared.u64 t, %1; cvt.u32.u64 %0, t; }"
        : "=r"(a) : "l"(p));
    return a;
}
__device__ __forceinline__ void ldsm4(uint32_t& r0, uint32_t& r1, uint32_t& r2, uint32_t& r3,
                                      uint32_t addr){
    asm volatile("ldmatrix.sync.aligned.m8n8.x4.shared.b16 {%0,%1,%2,%3}, [%4];"
                 : "=r"(r0), "=r"(r1), "=r"(r2), "=r"(r3) : "r"(addr));
}
__device__ __forceinline__ void ldsm4t(uint32_t& r0, uint32_t& r1, uint32_t& r2, uint32_t& r3,
                                       uint32_t addr){
    asm volatile("ldmatrix.sync.aligned.m8n8.x4.trans.shared.b16 {%0,%1,%2,%3}, [%4];"
                 : "=r"(r0), "=r"(r1), "=r"(r2), "=r"(r3) : "r"(addr));
}
__device__ __forceinline__ void mma16816(float* c, const uint32_t* a, const uint32_t* b){
    asm volatile("mma.sync.aligned.m16n8k16.row.col.f32.f16.f16.f32 "
                 "{%0,%1,%2,%3}, {%4,%5,%6,%7}, {%8,%9}, {%0,%1,%2,%3};"
                 : "+f"(c[0]), "+f"(c[1]), "+f"(c[2]), "+f"(c[3])
                 : "r"(a[0]), "r"(a[1]), "r"(a[2]), "r"(a[3]), "r"(b[0]), "r"(b[1]));
}
__device__ __forceinline__ void mma16816h(uint32_t* c, const uint32_t* a, const uint32_t* b){
    asm volatile("mma.sync.aligned.m16n8k16.row.col.f16.f16.f16.f16 "
                 "{%0,%1}, {%2,%3,%4,%5}, {%6,%7}, {%0,%1};"
                 : "+r"(c[0]), "+r"(c[1])
                 : "r"(a[0]), "r"(a[1]), "r"(a[2]), "r"(a[3]), "r"(b[0]), "r"(b[1]));
}
#define CP16(d,s)   asm volatile("cp.async.cg.shared.global [%0], [%1], 16;" :: "r"(d), "l"(s) : "memory")
#define CPCOMMIT()  asm volatile("cp.async.commit_group;" ::: "memory")
#define CPWAIT1()   asm volatile("cp.async.wait_group 1;" ::: "memory")

__device__ __forceinline__ float wrsum(float v){
    #pragma unroll
    for (int o = 16; o; o >>= 1) v += __shfl_xor_sync(0xffffffffu, v, o);
    return v;
}
__device__ __forceinline__ float wrmax(float v){
    #pragma unroll
    for (int o = 16; o; o >>= 1) v = fmaxf(v, __shfl_xor_sync(0xffffffffu, v, o));
    return v;
}

// ====================== BK=32 split GEMM (input projection only) ============
#define GEMM_SMEM (3*32768)

__global__ __launch_bounds__(256,2) void gemm_proj(
    const __half* __restrict__ Ah, const __half* __restrict__ Al,
    const __half* __restrict__ Bh, const __half* __restrict__ Bl,
    const float* __restrict__ bias, float* __restrict__ Cf,
    int K, int lda, int ldb, int ldc)
{
    extern __shared__ char sm[];
    int tid = threadIdx.x, lane = tid & 31, wid = tid >> 5;
    int m0 = blockIdx.y * 128, n0 = blockIdx.x * 128;
    int wm0 = (wid >> 2) * 64, wn0 = (wid & 3) * 32;

    float acc[4][4][4];
    #pragma unroll
    for (int i = 0; i < 4; i++)
        #pragma unroll
        for (int j = 0; j < 4; j++)
            #pragma unroll
            for (int e = 0; e < 4; e++) acc[i][j][e] = 0.f;

    uint32_t smBase = smem_u32(sm);
    int nch = K >> 5;

    auto stage = [&](int c, int s){
        uint32_t bs = smBase + s * 32768;
        int k0 = c * 32;
        #pragma unroll
        for (int j = 0; j < 2; j++) {
            int id = tid + j * 256;
            int r = id >> 2, cc = id & 3;
            uint32_t d = bs + (uint32_t)(r * 64 + ((cc ^ ((r >> 1) & 3)) << 4));
            CP16(d, Ah + (long long)(m0 + r) * lda + k0 + cc * 8);
            CP16(d + 8192, Al + (long long)(m0 + r) * lda + k0 + cc * 8);
            uint32_t db = bs + 16384 + (uint32_t)(r * 64 + ((cc ^ ((r >> 1) & 3)) << 4));
            CP16(db, Bh + (long long)(n0 + r) * ldb + k0 + cc * 8);
            CP16(db + 8192, Bl + (long long)(n0 + r) * ldb + k0 + cc * 8);
        }
        CPCOMMIT();
    };
    stage(0, 0);
    if (nch > 1) stage(1, 1); else CPCOMMIT();

    uint32_t aRowB = (uint32_t)(wm0 + (lane & 15)) * 64;
    uint32_t aXor  = ((uint32_t)(lane & 15) >> 1) & 3;
    uint32_t aG    = (uint32_t)(lane >> 4);
    uint32_t bRowB = (uint32_t)(wn0 + ((lane >> 4) << 3) + (lane & 7)) * 64;
    uint32_t bXor  = (((uint32_t)lane & 7) >> 1) & 3;
    uint32_t bG    = (uint32_t)((lane >> 3) & 1);

    for (int c = 0; c < nch; c++) {
        CPWAIT1();
        __syncthreads();
        uint32_t base = smBase + (uint32_t)((c % 3) * 32768);
        #pragma unroll
        for (int ks = 0; ks < 2; ks++) {
            uint32_t bh[8], bl[8];
            #pragma unroll
            for (int ntp = 0; ntp < 2; ntp++) {
                uint32_t ga = (uint32_t)(ks * 2) + bG;
                uint32_t off = bRowB + (uint32_t)(ntp * 1024) + ((ga ^ bXor) << 4);
                ldsm4(bh[ntp*4+0], bh[ntp*4+1], bh[ntp*4+2], bh[ntp*4+3], base + 16384 + off);
                ldsm4(bl[ntp*4+0], bl[ntp*4+1], bl[ntp*4+2], bl[ntp*4+3], base + 24576 + off);
            }
            #pragma unroll
            for (int mt = 0; mt < 4; mt++) {
                uint32_t ga = (uint32_t)(ks * 2) + aG;
                uint32_t off = aRowB + (uint32_t)(mt * 1024) + ((ga ^ aXor) << 4);
                uint32_t ah[4], al[4];
                ldsm4(ah[0], ah[1], ah[2], ah[3], base + off);
                ldsm4(al[0], al[1], al[2], al[3], base + 8192 + off);
                #pragma unroll
                for (int nt = 0; nt < 4; nt++) {
                    const uint32_t* ph = &bh[(nt >> 1) * 4 + (nt & 1) * 2];
                    const uint32_t* pl = &bl[(nt >> 1) * 4 + (nt & 1) * 2];
                    mma16816(acc[mt][nt], ah, ph);
                    mma16816(acc[mt][nt], ah, pl);
                    mma16816(acc[mt][nt], al, ph);
                }
            }
        }
        if (c + 2 < nch) stage(c + 2, (c + 2) % 3); else CPCOMMIT();
    }
    #pragma unroll
    for (int nt = 0; nt < 4; nt++) {
        int cc = n0 + wn0 + nt * 8 + (lane & 3) * 2;
        float b0 = bias[cc], b1 = bias[cc + 1];
        #pragma unroll
        for (int mt = 0; mt < 4; mt++) {
            int r = m0 + wm0 + mt * 16 + (lane >> 2);
            *(float2*)(Cf + (long long)r * ldc + cc) =
                make_float2(acc[mt][nt][0] + b0, acc[mt][nt][1] + b1);
            *(float2*)(Cf + (long long)(r + 8) * ldc + cc) =
                make_float2(acc[mt][nt][2] + b0, acc[mt][nt][3] + b1);
        }
    }
}

// ====================== BK=64 grid-mapped GEMM (main ops) ===================
// BTRANS: B [K,N] (NN, trans); else [N,K] (NT). OUT: 0 fp32, 2 fp16.
// rpart (optional): 8 per-ktile partial rowsums; epilogue divides by their sum.
#define G64_SMEM (3*32768)

template<bool BTRANS, int OUT, bool RELU>
__global__ __launch_bounds__(256,2) void gemm64(
    const __half* __restrict__ Ah_, const __half* __restrict__ Bh_,
    const float* __restrict__ bias, const float* __restrict__ rpart,
    float* __restrict__ Cf, __half* __restrict__ Ch,
    int K, int lda, int ldb, int ldc,
    long long sA, long long sB, long long sC)
{
    extern __shared__ char sm[];
    int tid = threadIdx.x, lane = tid & 31, wid = tid >> 5;
    int z = blockIdx.z;
    const __half* Ah = Ah_ + (long long)z * sA;
    const __half* Bh = Bh_ + (long long)z * sB;
    int m0 = blockIdx.y * 128, n0 = blockIdx.x * 128;
    int wm0 = (wid >> 2) * 64, wn0 = (wid & 3) * 32;

    float acc[4][4][4];
    #pragma unroll
    for (int i = 0; i < 4; i++)
        #pragma unroll
        for (int j = 0; j < 4; j++)
            #pragma unroll
            for (int e = 0; e < 4; e++) acc[i][j][e] = 0.f;

    uint32_t smBase = smem_u32(sm);
    int nch = K >> 6;

    auto stage = [&](int c, int s){
        uint32_t bs = smBase + s * 32768;
        int k0 = c * 64;
        #pragma unroll
        for (int j = 0; j < 4; j++) {
            int id = tid + j * 256;
            int r = id >> 3, cc = id & 7;
            uint32_t off = (uint32_t)(r * 128 + ((cc ^ (r & 7)) << 4));
            CP16(bs + off, Ah + (long long)(m0 + r) * lda + k0 + cc * 8);
        }
        if (!BTRANS) {
            #pragma unroll
            for (int j = 0; j < 4; j++) {
                int id = tid + j * 256;
                int r = id >> 3, cc = id & 7;
                uint32_t off = (uint32_t)(r * 128 + ((cc ^ (r & 7)) << 4));
                CP16(bs + 16384 + off, Bh + (long long)(n0 + r) * ldb + k0 + cc * 8);
            }
        } else {
            #pragma unroll
            for (int j = 0; j < 4; j++) {
                int id = tid + j * 256;
                int k = id >> 4, cc = id & 15;
                uint32_t off = (uint32_t)(k * 256 + ((cc ^ (k & 7)) << 4));
                CP16(bs + 16384 + off, Bh + (long long)(k0 + k) * ldb + n0 + cc * 8);
            }
        }
        CPCOMMIT();
    };
    stage(0, 0);
    if (nch > 1) stage(1, 1); else CPCOMMIT();

    uint32_t aRow = (uint32_t)(wm0 + (lane & 15));
    uint32_t bRowNT = (uint32_t)(wn0 + ((lane >> 4) << 3) + (lane & 7));
    uint32_t btRow = ((((uint32_t)lane >> 3) & 1) * 8 + ((uint32_t)lane & 7)) * 256;
    uint32_t btNc  = ((uint32_t)wn0 >> 3) + ((uint32_t)lane >> 4);
    uint32_t btXk  = (uint32_t)lane & 7;

    for (int c = 0; c < nch; c++) {
        CPWAIT1();
        __syncthreads();
        uint32_t base = smBase + (uint32_t)((c % 3) * 32768);
        #pragma unroll
        for (int ks = 0; ks < 4; ks++) {
            uint32_t bh[8];
            if (!BTRANS) {
                #pragma unroll
                for (int ntp = 0; ntp < 2; ntp++) {
                    uint32_t row = bRowNT + (uint32_t)(ntp * 16);
                    uint32_t g = (uint32_t)(ks * 2) + (uint32_t)((lane >> 3) & 1);
                    uint32_t off = row * 128 + ((g ^ (row & 7)) << 4);
                    ldsm4(bh[ntp*4+0], bh[ntp*4+1], bh[ntp*4+2], bh[ntp*4+3],
                          base + 16384 + off);
                }
            } else {
                #pragma unroll
                for (int ntp = 0; ntp < 2; ntp++) {
                    uint32_t off = btRow + (uint32_t)(ks * 4096)
                                 + (((btNc + (uint32_t)(ntp * 2)) ^ btXk) << 4);
                    ldsm4t(bh[ntp*4+0], bh[ntp*4+1], bh[ntp*4+2], bh[ntp*4+3],
                           base + 16384 + off);
                }
            }
            #pragma unroll
            for (int mt = 0; mt < 4; mt++) {
                uint32_t row = aRow + (uint32_t)(mt * 16);
                uint32_t g = (uint32_t)(ks * 2) + (uint32_t)(lane >> 4);
                uint32_t off = row * 128 + ((g ^ (row & 7)) << 4);
                uint32_t ah[4];
                ldsm4(ah[0], ah[1], ah[2], ah[3], base + off);
                #pragma unroll
                for (int nt = 0; nt < 4; nt++)
                    mma16816(acc[mt][nt], ah, &bh[(nt >> 1) * 4 + (nt & 1) * 2]);
            }
        }
        if (c + 2 < nch) stage(c + 2, (c + 2) % 3); else CPCOMMIT();
    }

    float rd0[4], rd1[4];
    if (rpart) {
        #pragma unroll
        for (int mt = 0; mt < 4; mt++) {
            int r = m0 + wm0 + mt * 16 + (lane >> 2);
            long long rb = (long long)z * 1024 + r;
            float s0 = 0.f, s1 = 0.f;
            #pragma unroll
            for (int kt = 0; kt < 8; kt++) {
                s0 += rpart[kt * ROWS + rb];
                s1 += rpart[kt * ROWS + rb + 8];
            }
            rd0[mt] = 1.f / s0;
            rd1[mt] = 1.f / s1;
        }
    }

    #pragma unroll
    for (int nt = 0; nt < 4; nt++) {
        int cc = n0 + wn0 + nt * 8 + (lane & 3) * 2;
        float b0 = 0.f, b1 = 0.f;
        if (bias) { b0 = bias[cc]; b1 = bias[cc + 1]; }
        #pragma unroll
        for (int mt = 0; mt < 4; mt++) {
            int r = m0 + wm0 + mt * 16 + (lane >> 2);
            float v0 = acc[mt][nt][0] + b0;
            float v1 = acc[mt][nt][1] + b1;
            float v2 = acc[mt][nt][2] + b0;
            float v3 = acc[mt][nt][3] + b1;
            if (rpart) { v0 *= rd0[mt]; v1 *= rd0[mt]; v2 *= rd1[mt]; v3 *= rd1[mt]; }
            if (RELU) { v0 = fmaxf(v0,0.f); v1 = fmaxf(v1,0.f); v2 = fmaxf(v2,0.f); v3 = fmaxf(v3,0.f); }
            if (OUT == 0) {
                float* p = Cf + (long long)z * sC;
                *(float2*)(p + (long long)r * ldc + cc)       = make_float2(v0, v1);
                *(float2*)(p + (long long)(r + 8) * ldc + cc) = make_float2(v2, v3);
            } else {
                __half* ph = Ch + (long long)z * sC;
                *(__half2*)(ph + (long long)r * ldc + cc) =
                    __halves2half2(__float2half_rn(v0), __float2half_rn(v1));
                *(__half2*)(ph + (long long)(r + 8) * ldc + cc) =
                    __halves2half2(__float2half_rn(v2), __float2half_rn(v3));
            }
        }
    }
}

// ====================== fused attention pass A: 1/sumexp ====================
#define SE_SMEM (3*16384)

__global__ __launch_bounds__(256,2) void sumexp_k(
    const __half* __restrict__ qk, float* __restrict__ sinv)
{
    extern __shared__ char sm[];
    int tid = threadIdx.x, lane = tid & 31, wid = tid >> 5;
    int wm0 = wid * 16;
    int z = blockIdx.y, b = z >> 3, h = z & 7;
    int m0 = blockIdx.x * 128;
    const __half* qb = qk + (long long)b * SS * 1024 + h * 64;
    const __half* kb = qb + 512;
    uint32_t smBase = smem_u32(sm);

    #pragma unroll
    for (int j = 0; j < 4; j++) {
        int id = tid + j * 256;
        int r = id >> 3, cc = id & 7;
        uint32_t off = (uint32_t)(r * 128 + ((cc ^ (r & 7)) << 4));
        CP16(smBase + off, qb + (long long)(m0 + r) * 1024 + cc * 8);
    }
    auto stageK = [&](int kt, int s){
        uint32_t bs = smBase + 16384 + s * 16384;
        int n0 = kt * 128;
        #pragma unroll
        for (int j = 0; j < 4; j++) {
            int id = tid + j * 256;
            int r = id >> 3, cc = id & 7;
            uint32_t off = (uint32_t)(r * 128 + ((cc ^ (r & 7)) << 4));
            CP16(bs + off, kb + (long long)(n0 + r) * 1024 + cc * 8);
        }
        CPCOMMIT();
    };
    stageK(0, 0);
    stageK(1, 1);

    uint32_t aRow = (uint32_t)(wm0 + (lane & 15));
    uint32_t bRow0 = (uint32_t)(((lane >> 4) << 3) + (lane & 7));
    float sum0 = 0.f, sum1 = 0.f;

    for (int kt = 0; kt < 8; kt++) {
        CPWAIT1();
        __syncthreads();
        uint32_t kbase = smBase + 16384 + (uint32_t)((kt & 1) * 16384);
        uint32_t hacc[16][2];
        #pragma unroll
        for (int i = 0; i < 16; i++) { hacc[i][0] = 0u; hacc[i][1] = 0u; }
        #pragma unroll
        for (int ks = 0; ks < 4; ks++) {
            uint32_t ag = (uint32_t)(ks * 2) + (uint32_t)(lane >> 4);
            uint32_t ah[4];
            ldsm4(ah[0], ah[1], ah[2], ah[3],
                  smBase + aRow * 128 + ((ag ^ (aRow & 7)) << 4));
            #pragma unroll
            for (int ntp = 0; ntp < 8; ntp++) {
                uint32_t row = bRow0 + (uint32_t)(ntp * 16);
                uint32_t bg = (uint32_t)(ks * 2) + (uint32_t)((lane >> 3) & 1);
                uint32_t r4[4];
                ldsm4(r4[0], r4[1], r4[2], r4[3],
                      kbase + row * 128 + ((bg ^ (row & 7)) << 4));
                mma16816h(hacc[ntp*2],     ah, &r4[0]);
                mma16816h(hacc[ntp*2 + 1], ah, &r4[2]);
            }
        }
        #pragma unroll
        for (int nt = 0; nt < 16; nt++) {
            float2 f0 = __half22float2(*reinterpret_cast<__half2*>(&hacc[nt][0]));
            float2 f1 = __half22float2(*reinterpret_cast<__half2*>(&hacc[nt][1]));
            sum0 += __expf(f0.x * 0.125f) + __expf(f0.y * 0.125f);
            sum1 += __expf(f1.x * 0.125f) + __expf(f1.y * 0.125f);
        }
        __syncthreads();
        if (kt + 2 < 8) stageK(kt + 2, kt & 1); else CPCOMMIT();
    }
    sum0 += __shfl_xor_sync(0xffffffffu, sum0, 1);
    sum0 += __shfl_xor_sync(0xffffffffu, sum0, 2);
    sum1 += __shfl_xor_sync(0xffffffffu, sum1, 1);
    sum1 += __shfl_xor_sync(0xffffffffu, sum1, 2);
    if ((lane & 3) == 0) {
        int r = m0 + wm0 + (lane >> 2);
        sinv[(long long)z * SS + r]     = 1.f / sum0;
        sinv[(long long)z * SS + r + 8] = 1.f / sum1;
    }
}

// ====================== fused attention pass B: w~ + partial rowsums ========
#define FW_SMEM (2*32768)

__global__ __launch_bounds__(256,2) void fuse_w_k(
    const __half* __restrict__ qk, const float* __restrict__ sinv,
    const __half* __restrict__ dbias, __half* __restrict__ wh,
    float* __restrict__ rpart)
{
    extern __shared__ char sm[];
    int tid = threadIdx.x, lane = tid & 31, wid = tid >> 5;
    int wm0 = wid * 16;
    int b = blockIdx.z, qt = blockIdx.y, kt = blockIdx.x;
    int m0 = qt * 128, n0 = kt * 128;
    const __half* base_q = qk + (long long)b * SS * 1024;
    uint32_t smBase = smem_u32(sm);

    auto stageH = [&](int h, int s){
        uint32_t bs = smBase + s * 32768;
        const __half* qb = base_q + h * 64;
        const __half* kb = qb + 512;
        #pragma unroll
        for (int j = 0; j < 8; j++) {
            int id = tid + j * 256;
            int r = (id & 1023) >> 3, cc = id & 7;
            uint32_t off = (uint32_t)(r * 128 + ((cc ^ (r & 7)) << 4));
            if (id < 1024) CP16(bs + off, qb + (long long)(m0 + r) * 1024 + cc * 8);
            else           CP16(bs + 16384 + off, kb + (long long)(n0 + r) * 1024 + cc * 8);
        }
        CPCOMMIT();
    };
    stageH(0, 0);
    stageH(1, 1);

    uint32_t aRow = (uint32_t)(wm0 + (lane & 15));
    uint32_t bRow0 = (uint32_t)(((lane >> 4) << 3) + (lane & 7));
    int r0 = wm0 + (lane >> 2);
    uint32_t wacc[16][2];
    #pragma unroll
    for (int i = 0; i < 16; i++) { wacc[i][0] = 0u; wacc[i][1] = 0u; }

    for (int h = 0; h < 8; h++) {
        CPWAIT1();
        __syncthreads();
        uint32_t qbase = smBase + (uint32_t)((h & 1) * 32768);
        uint32_t kbase = qbase + 16384;
        uint32_t hacc[16][2];
        #pragma unroll
        for (int i = 0; i < 16; i++) { hacc[i][0] = 0u; hacc[i][1] = 0u; }
        #pragma unroll
        for (int ks = 0; ks < 4; ks++) {
            uint32_t ag = (uint32_t)(ks * 2) + (uint32_t)(lane >> 4);
            uint32_t ah[4];
            ldsm4(ah[0], ah[1], ah[2], ah[3],
                  qbase + aRow * 128 + ((ag ^ (aRow & 7)) << 4));
            #pragma unroll
            for (int ntp = 0; ntp < 8; ntp++) {
                uint32_t row = bRow0 + (uint32_t)(ntp * 16);
                uint32_t bg = (uint32_t)(ks * 2) + (uint32_t)((lane >> 3) & 1);
                uint32_t r4[4];
                ldsm4(r4[0], r4[1], r4[2], r4[3],
                      kbase + row * 128 + ((bg ^ (row & 7)) << 4));
                mma16816h(hacc[ntp*2],     ah, &r4[0]);
                mma16816h(hacc[ntp*2 + 1], ah, &r4[2]);
            }
        }
        long long sbase = (long long)(b * 8 + h) * SS + m0;
        float is0 = sinv[sbase + r0];
        float is1 = sinv[sbase + r0 + 8];
        #pragma unroll
        for (int nt = 0; nt < 16; nt++) {
            float2 f0 = __half22float2(*reinterpret_cast<__half2*>(&hacc[nt][0]));
            float2 f1 = __half22float2(*reinterpret_cast<__half2*>(&hacc[nt][1]));
            __half2 t0 = __floats2half2_rn(__expf(f0.x * 0.125f) * is0,
                                           __expf(f0.y * 0.125f) * is0);
            __half2 t1 = __floats2half2_rn(__expf(f1.x * 0.125f) * is1,
                                           __expf(f1.y * 0.125f) * is1);
            *reinterpret_cast<__half2*>(&wacc[nt][0]) =
                __hadd2(*reinterpret_cast<__half2*>(&wacc[nt][0]), t0);
            *reinterpret_cast<__half2*>(&wacc[nt][1]) =
                __hadd2(*reinterpret_cast<__half2*>(&wacc[nt][1]), t1);
        }
        __syncthreads();
        if (h + 2 < 8) stageH(h + 2, h & 1); else CPCOMMIT();
    }

    // multiply by dist bias, store w~, and emit per-ktile partial rowsums
    long long row0 = (long long)(b * SS + m0 + r0);
    const __half* db0 = dbias + row0 * SS;
    __half* wp0 = wh + row0 * SS;
    int ccb = n0 + (lane & 3) * 2;
    float ps0 = 0.f, ps1 = 0.f;
    #pragma unroll
    for (int nt = 0; nt < 16; nt++) {
        int col = ccb + nt * 8;
        __half2 d0 = *(const __half2*)(db0 + col);
        __half2 d1 = *(const __half2*)(db0 + 8 * SS + col);
        __half2 v0 = __hmul2(*reinterpret_cast<__half2*>(&wacc[nt][0]), d0);
        __half2 v1 = __hmul2(*reinterpret_cast<__half2*>(&wacc[nt][1]), d1);
        *(__half2*)(wp0 + col) = v0;
        *(__half2*)(wp0 + 8 * SS + col) = v1;
        float2 f0 = __half22float2(v0), f1 = __half22float2(v1);
        ps0 += f0.x + f0.y;
        ps1 += f1.x + f1.y;
    }
    ps0 += __shfl_xor_sync(0xffffffffu, ps0, 1);
    ps0 += __shfl_xor_sync(0xffffffffu, ps0, 2);
    ps1 += __shfl_xor_sync(0xffffffffu, ps1, 1);
    ps1 += __shfl_xor_sync(0xffffffffu, ps1, 2);
    if ((lane & 3) == 0) {
        rpart[kt * ROWS + row0]     = ps0;
        rpart[kt * ROWS + row0 + 8] = ps1;
    }
}

// ---------------- fp32 -> fp16 converters (8 elems/thread) ------------------
__global__ void split_k(const float* __restrict__ in, __half* __restrict__ h,
                        __half* __restrict__ l, int n8) {
    int i = blockIdx.x * 256 + threadIdx.x;
    if (i >= n8) return;
    long long base = (long long)i * 8;
    float4 a = *(const float4*)(in + base);
    float4 b = *(const float4*)(in + base + 4);
    float va[8] = {a.x, a.y, a.z, a.w, b.x, b.y, b.z, b.w};
    uint4 hp, lp;
    uint32_t* hw = reinterpret_cast<uint32_t*>(&hp);
    uint32_t* lw = reinterpret_cast<uint32_t*>(&lp);
    #pragma unroll
    for (int j = 0; j < 4; j++) {
        __half h0 = __float2half_rn(va[j*2]), h1 = __float2half_rn(va[j*2+1]);
        __half2 hh = __halves2half2(h0, h1);
        __half2 ll = __halves2half2(__float2half_rn(va[j*2]   - __half2float(h0)),
                                    __float2half_rn(va[j*2+1] - __half2float(h1)));
        hw[j] = *reinterpret_cast<uint32_t*>(&hh);
        lw[j] = *reinterpret_cast<uint32_t*>(&ll);
    }
    *(uint4*)(h + base) = hp;
    *(uint4*)(l + base) = lp;
}
__global__ void cvt_k(const float* __restrict__ in, __half* __restrict__ h, int n8) {
    int i = blockIdx.x * 256 + threadIdx.x;
    if (i >= n8) return;
    long long base = (long long)i * 8;
    float4 a = *(const float4*)(in + base);
    float4 b = *(const float4*)(in + base + 4);
    uint4 hp;
    uint32_t* hw = reinterpret_cast<uint32_t*>(&hp);
    __half2 h0 = __floats2half2_rn(a.x, a.y);
    __half2 h1 = __floats2half2_rn(a.z, a.w);
    __half2 h2 = __floats2half2_rn(b.x, b.y);
    __half2 h3 = __floats2half2_rn(b.z, b.w);
    hw[0] = *reinterpret_cast<uint32_t*>(&h0);
    hw[1] = *reinterpret_cast<uint32_t*>(&h1);
    hw[2] = *reinterpret_cast<uint32_t*>(&h2);
    hw[3] = *reinterpret_cast<uint32_t*>(&h3);
    *(uint4*)(h + base) = hp;
}

// ---------------- BatchNorm (training-mode batch stats), deterministic -----
__global__ void bn_part_k(const float* __restrict__ x, float* __restrict__ part) {
    int e = threadIdx.x;
    int blk = blockIdx.x;
    float s = 0.f, sq = 0.f;
    int r0 = blk * 128;
    for (int r = r0; r < r0 + 128; r++) {
        float v = x[(long long)r * EE + e];
        s += v; sq += v * v;
    }
    part[blk * EE + e] = s;
    part[(64 + blk) * EE + e] = sq;
}

__global__ void bn_final_k(const float* __restrict__ part, float* __restrict__ stats) {
    int e = blockIdx.x * blockDim.x + threadIdx.x;
    float s = 0.f, sq = 0.f;
    for (int i = 0; i < 64; i++) {
        s  += part[i * EE + e];
        sq += part[(64 + i) * EE + e];
    }
    float mu = s / (float)ROWS;
    stats[e] = mu;
    stats[EE + e] = sq / (float)ROWS - mu * mu;
}

__global__ void bn_apply_pe_k(float* __restrict__ x, const float* __restrict__ stats,
                              const float* __restrict__ g, const float* __restrict__ b,
                              __half* __restrict__ xh) {
    long long idx = (long long)blockIdx.x * blockDim.x + threadIdx.x;
    int e = (int)(idx & (EE - 1));
    long long r = idx >> 9;
    int s = (int)(r & (SS - 1));
    float mu = stats[e], var = stats[EE + e];
    int j = e >> 1;
    float dt = expf((float)(2 * j) * (-9.210340371976184f / (float)EE));
    float ang = (float)s * dt;
    float pe = (e & 1) ? cosf(ang) : sinf(ang);
    float v = (x[idx] - mu) * rsqrtf(var + EPS) * g[e] + b[e] + pe;
    x[idx] = v;
    xh[idx] = __float2half_rn(v);
}

// ---------------- distance bias (warp per row, fp16 out) --------------------
__global__ void dist_bias_k(const float* __restrict__ d, const float* __restrict__ scale_p,
                            __half* __restrict__ bias) {
    int row = blockIdx.x * 8 + (threadIdx.x >> 5);
    int lane = threadIdx.x & 31;
    const float* dp = d + (long long)row * SS + lane * 4;
    float4 v[8];
    float mx = -1e30f;
    #pragma unroll
    for (int i = 0; i < 8; i++) {
        v[i] = *(const float4*)(dp + i * 128);
        mx = fmaxf(mx, fmaxf(fmaxf(v[i].x, v[i].y), fmaxf(v[i].z, v[i].w)));
    }
    mx = wrmax(mx);
    float inv_dmax = 1.f / mx;
    float sc = scale_p[0];
    __half* bp = bias + (long long)row * SS + lane * 4;
    #pragma unroll
    for (int i = 0; i < 8; i++) {
        __half2 h0 = __halves2half2(__float2half_rn(expf(sc * (1.f - v[i].x * inv_dmax))),
                                    __float2half_rn(expf(sc * (1.f - v[i].y * inv_dmax))));
        __half2 h1 = __halves2half2(__float2half_rn(expf(sc * (1.f - v[i].z * inv_dmax))),
                                    __float2half_rn(expf(sc * (1.f - v[i].w * inv_dmax))));
        uint2 pk; pk.x = *reinterpret_cast<uint32_t*>(&h0); pk.y = *reinterpret_cast<uint32_t*>(&h1);
        *(uint2*)(bp + i * 128) = pk;
    }
}

// ---------------- fused residual + LayerNorm (warp per row) -----------------
template<bool SPLIT>
__global__ void add_ln_k(const float* __restrict__ x, const float* __restrict__ r,
                         const float* __restrict__ g, const float* __restrict__ b,
                         float* __restrict__ out, __half* __restrict__ oh) {
    int row = blockIdx.x * 8 + (threadIdx.x >> 5);
    int lane = threadIdx.x & 31;
    long long base = (long long)row * EE + lane * 4;
    float4 v[4];
    float s = 0.f, sq = 0.f;
    #pragma unroll
    for (int i = 0; i < 4; i++) {
        float4 a = *(const float4*)(x + base + i * 128);
        float4 rr = *(const float4*)(r + base + i * 128);
        a.x += rr.x; a.y += rr.y; a.z += rr.z; a.w += rr.w;
        v[i] = a;
        s += a.x + a.y + a.z + a.w;
        sq += a.x*a.x + a.y*a.y + a.z*a.z + a.w*a.w;
    }
    float mean = wrsum(s) * (1.f / (float)EE);
    float var = wrsum(sq) * (1.f / (float)EE) - mean * mean;
    float inv = rsqrtf(var + EPS);
    #pragma unroll
    for (int i = 0; i < 4; i++) {
        float4 gg = *(const float4*)(g + lane * 4 + i * 128);
        float4 bb = *(const float4*)(b + lane * 4 + i * 128);
        float4 o;
        o.x = (v[i].x - mean) * inv * gg.x + bb.x;
        o.y = (v[i].y - mean) * inv * gg.y + bb.y;
        o.z = (v[i].z - mean) * inv * gg.z + bb.z;
        o.w = (v[i].w - mean) * inv * gg.w + bb.w;
        *(float4*)(out + base + i * 128) = o;
        if (SPLIT) {
            __half2 h0 = __halves2half2(__float2half_rn(o.x), __float2half_rn(o.y));
            __half2 h1 = __halves2half2(__float2half_rn(o.z), __float2half_rn(o.w));
            uint2 pk; pk.x = *reinterpret_cast<uint32_t*>(&h0); pk.y = *reinterpret_cast<uint32_t*>(&h1);
            *(uint2*)(oh + base + i * 128) = pk;
        }
    }
}

// ---------------- launch -----------------------------------------------------
extern "C" void kernel_launch(void* const* d_in, const int* in_sizes, int n_in,
                              void* d_out, int out_size) {
    (void)in_sizes; (void)n_in; (void)out_size;
    const float* src        = (const float*)d_in[0];
    const float* distances  = (const float*)d_in[1];
    const float* proj_w     = (const float*)d_in[2];
    const float* proj_b     = (const float*)d_in[3];
    const float* bn_g       = (const float*)d_in[4];
    const float* bn_b       = (const float*)d_in[5];
    const float* in_proj_w  = (const float*)d_in[6];
    const float* in_proj_b  = (const float*)d_in[7];
    const float* dist_scale = (const float*)d_in[8];
    const float* lin1_w     = (const float*)d_in[9];
    const float* lin1_b     = (const float*)d_in[10];
    const float* lin2_w     = (const float*)d_in[11];
    const float* lin2_b     = (const float*)d_in[12];
    const float* n1_g       = (const float*)d_in[13];
    const float* n1_b       = (const float*)d_in[14];
    const float* n2_g       = (const float*)d_in[15];
    const float* n2_b       = (const float*)d_in[16];
    float* out = (float*)d_out;

    float *x, *attn, *part, *stats, *sinv, *rpart;
    __half *dbias, *srch, *srcl, *xh, *qkh, *wh, *ffh;
    __half *pwh, *pwl, *iph, *l1h, *l2h;
    cudaGetSymbolAddress((void**)&x,     g_x);
    cudaGetSymbolAddress((void**)&dbias, g_dbias);
    cudaGetSymbolAddress((void**)&attn,  g_attn);
    cudaGetSymbolAddress((void**)&part,  g_part);
    cudaGetSymbolAddress((void**)&stats, g_stats);
    cudaGetSymbolAddress((void**)&sinv,  g_sinv);
    cudaGetSymbolAddress((void**)&rpart, g_rpart);
    cudaGetSymbolAddress((void**)&srch,  g_srch); cudaGetSymbolAddress((void**)&srcl, g_srcl);
    cudaGetSymbolAddress((void**)&xh,    g_xh);
    cudaGetSymbolAddress((void**)&qkh,   g_qkh);
    cudaGetSymbolAddress((void**)&wh,    g_wh);
    cudaGetSymbolAddress((void**)&ffh,   g_ffh);
    cudaGetSymbolAddress((void**)&pwh,   g_pwh);  cudaGetSymbolAddress((void**)&pwl,  g_pwl);
    cudaGetSymbolAddress((void**)&iph,   g_iph);
    cudaGetSymbolAddress((void**)&l1h,   g_l1h);
    cudaGetSymbolAddress((void**)&l2h,   g_l2h);

    cudaFuncSetAttribute(gemm_proj, cudaFuncAttributeMaxDynamicSharedMemorySize, GEMM_SMEM);
    cudaFuncSetAttribute(gemm64<false,2,false>, cudaFuncAttributeMaxDynamicSharedMemorySize, G64_SMEM);
    cudaFuncSetAttribute(gemm64<false,2,true>,  cudaFuncAttributeMaxDynamicSharedMemorySize, G64_SMEM);
    cudaFuncSetAttribute(gemm64<true,0,false>,  cudaFuncAttributeMaxDynamicSharedMemorySize, G64_SMEM);
    cudaFuncSetAttribute(gemm64<false,0,false>, cudaFuncAttributeMaxDynamicSharedMemorySize, G64_SMEM);
    cudaFuncSetAttribute(sumexp_k, cudaFuncAttributeMaxDynamicSharedMemorySize, SE_SMEM);
    cudaFuncSetAttribute(fuse_w_k, cudaFuncAttributeMaxDynamicSharedMemorySize, FW_SMEM);

    dim3 blk(256);
    const long long SE  = (long long)SS * EE;
    const long long SS2 = (long long)SS * SS;

    // 0) one-time conversions
    split_k<<<(ROWS*IN_F/8+255)/256, 256>>>(src, srch, srcl, ROWS*IN_F/8);
    split_k<<<(EE*IN_F/8+255)/256, 256>>>(proj_w, pwh, pwl, EE*IN_F/8);
    cvt_k<<<(1024*EE/8+255)/256, 256>>>(in_proj_w, iph, 1024*EE/8);
    cvt_k<<<(FF_DIM*EE/8+255)/256, 256>>>(lin1_w, l1h, FF_DIM*EE/8);
    cvt_k<<<(EE*FF_DIM/8+255)/256, 256>>>(lin2_w, l2h, EE*FF_DIM/8);

    // 1) input projection -> g_x (fp32), 3-pass
    gemm_proj<<<dim3(EE/128, ROWS/128, 1), blk, GEMM_SMEM>>>(
        srch, srcl, pwh, pwl, proj_b, x, IN_F, IN_F, IN_F, EE);

    // 2) BatchNorm + PE (+fp16 mirror)
    bn_part_k<<<64, 512>>>(x, part);
    bn_final_k<<<2, 256>>>(part, stats);
    bn_apply_pe_k<<<(ROWS*EE)/256, 256>>>(x, stats, bn_g, bn_b, xh);

    // 3) distance bias
    dist_bias_k<<<BB*SS/8, 256>>>(distances, dist_scale, dbias);

    // 4) layers
    for (int l = 0; l < NL; l++) {
        // qk projection -> fp16 (grid-mapped; proven fastest)
        gemm64<false,2,false><<<dim3(1024/128, ROWS/128, 1), blk, G64_SMEM>>>(
            xh, iph, in_proj_b, nullptr, nullptr, qkh,
            EE, EE, EE, 1024, 0, 0, 0);

        // fused attention weights (+partial rowsums; no rowinv launch)
        sumexp_k<<<dim3(8, BB*HH), blk, SE_SMEM>>>(qkh, sinv);
        fuse_w_k<<<dim3(8, 8, BB), blk, FW_SMEM>>>(qkh, sinv, dbias, wh, rpart);

        // attn_out = (w~ @ x) / rowsum -> fp32
        gemm64<true,0,false><<<dim3(EE/128, SS/128, BB), blk, G64_SMEM>>>(
            wh, xh, nullptr, rpart, attn, nullptr,
            SS, SS, EE, EE, SS2, SE, SE);

        // x = LN(x + attn_out)
        add_ln_k<true><<<ROWS/8, 256>>>(x, attn, n1_g, n1_b, x, xh);

        // FFN (grid-mapped)
        gemm64<false,2,true><<<dim3(FF_DIM/128, ROWS/128, 1), blk, G64_SMEM>>>(
            xh, l1h, lin1_b, nullptr, nullptr, ffh,
            EE, EE, EE, FF_DIM, 0, 0, 0);
        gemm64<false,0,false><<<dim3(EE/128, ROWS/128, 1), blk, G64_SMEM>>>(
            ffh, l2h, lin2_b, nullptr, attn, nullptr,
            FF_DIM, FF_DIM, FF_DIM, EE, 0, 0, 0);

        // x = LN(x + ff); last layer -> d_out
        if (l == NL - 1)
            add_ln_k<false><<<ROWS/8, 256>>>(x, attn, n2_g, n2_b, out, nullptr);
        else
            add_ln_k<true><<<ROWS/8, 256>>>(x, attn, n2_g, n2_b, x, xh);
    }
}

// round 17
// speedup vs baseline: 1.0257x; 1.0018x over previous
#include <cuda_runtime.h>
#include <cuda_fp16.h>
#include <cstdint>

// Problem constants
#define BB 8
#define SS 1024
#define IN_F 128
#define EE 512
#define HH 8
#define HD 64
#define FF_DIM 2048
#define NL 4
#define ROWS (BB*SS)          // 8192
#define EPS 1e-5f

// ---------------- scratch (device globals; no allocations allowed) ----------
__device__ __align__(16) float g_x[ROWS*EE];                   // fp32 residual stream
__device__ __align__(16) __half g_dbias[(size_t)BB*SS*SS];     // 16 MB fp16 dist bias
__device__ __align__(16) float g_attn[ROWS*EE];                // 16 MB fp32 delta
__device__ __align__(16) float g_part[2*64*EE];
__device__ __align__(16) float g_stats[2*EE];
__device__ __align__(16) float g_sinv[BB*HH*SS];               // 1/sumexp per (b,h,q)
__device__ __align__(16) float g_rpart[8*ROWS];                // per-ktile partial rowsums
// fp16 operand buffers
__device__ __align__(16) __half g_srch[ROWS*IN_F];
__device__ __align__(16) __half g_xh[ROWS*EE];
__device__ __align__(16) __half g_qkh[ROWS*1024];
__device__ __align__(16) __half g_wh[(size_t)BB*SS*SS];        // unnormalized w~ fp16
__device__ __align__(16) __half g_ffh[ROWS*FF_DIM];
__device__ __align__(16) __half g_pwh[EE*IN_F],     g_pwl[EE*IN_F];
__device__ __align__(16) __half g_iph[1024*EE];
__device__ __align__(16) __half g_l1h[FF_DIM*EE];
__device__ __align__(16) __half g_l2h[EE*FF_DIM];

// ====================== helpers =============================================
__device__ __forceinline__ uint32_t smem_u32(const void* p){
    uint32_t a;
    asm("{ .reg .u64 t; cvta.to.shared.u64 t, %1; cvt.u32.u64 %0, t; }"
        : "=r"(a) : "l"(p));
    return a;
}
__device__ __forceinline__ void ldsm4(uint32_t& r0, uint32_t& r1, uint32_t& r2, uint32_t& r3,
                                      uint32_t addr){
    asm volatile("ldmatrix.sync.aligned.m8n8.x4.shared.b16 {%0,%1,%2,%3}, [%4];"
                 : "=r"(r0), "=r"(r1), "=r"(r2), "=r"(r3) : "r"(addr));
}
__device__ __forceinline__ void ldsm4t(uint32_t& r0, uint32_t& r1, uint32_t& r2, uint32_t& r3,
                                       uint32_t addr){
    asm volatile("ldmatrix.sync.aligned.m8n8.x4.trans.shared.b16 {%0,%1,%2,%3}, [%4];"
                 : "=r"(r0), "=r"(r1), "=r"(r2), "=r"(r3) : "r"(addr));
}
__device__ __forceinline__ void mma16816(float* c, const uint32_t* a, const uint32_t* b){
    asm volatile("mma.sync.aligned.m16n8k16.row.col.f32.f16.f16.f32 "
                 "{%0,%1,%2,%3}, {%4,%5,%6,%7}, {%8,%9}, {%0,%1,%2,%3};"
                 : "+f"(c[0]), "+f"(c[1]), "+f"(c[2]), "+f"(c[3])
                 : "r"(a[0]), "r"(a[1]), "r"(a[2]), "r"(a[3]), "r"(b[0]), "r"(b[1]));
}
__device__ __forceinline__ void mma16816h(uint32_t* c, const uint32_t* a, const uint32_t* b){
    asm volatile("mma.sync.aligned.m16n8k16.row.col.f16.f16.f16.f16 "
                 "{%0,%1}, {%2,%3,%4,%5}, {%6,%7}, {%0,%1};"
                 : "+r"(c[0]), "+r"(c[1])
                 : "r"(a[0]), "r"(a[1]), "r"(a[2]), "r"(a[3]), "r"(b[0]), "r"(b[1]));
}
#define CP16(d,s)   asm volatile("cp.async.cg.shared.global [%0], [%1], 16;" :: "r"(d), "l"(s) : "memory")
#define CPCOMMIT()  asm volatile("cp.async.commit_group;" ::: "memory")
#define CPWAIT1()   asm volatile("cp.async.wait_group 1;" ::: "memory")

__device__ __forceinline__ float wrsum(float v){
    #pragma unroll
    for (int o = 16; o; o >>= 1) v += __shfl_xor_sync(0xffffffffu, v, o);
    return v;
}
__device__ __forceinline__ float wrmax(float v){
    #pragma unroll
    for (int o = 16; o; o >>= 1) v = fmaxf(v, __shfl_xor_sync(0xffffffffu, v, o));
    return v;
}

// ====================== BK=32 2-pass GEMM (input projection only) ===========
// A single fp16; B split hi/lo (2 MMA passes: AhBh + AhBl).
#define GEMM_SMEM (3*32768)

__global__ __launch_bounds__(256,2) void gemm_proj(
    const __half* __restrict__ Ah,
    const __half* __restrict__ Bh, const __half* __restrict__ Bl,
    const float* __restrict__ bias, float* __restrict__ Cf,
    int K, int lda, int ldb, int ldc)
{
    extern __shared__ char sm[];
    int tid = threadIdx.x, lane = tid & 31, wid = tid >> 5;
    int m0 = blockIdx.y * 128, n0 = blockIdx.x * 128;
    int wm0 = (wid >> 2) * 64, wn0 = (wid & 3) * 32;

    float acc[4][4][4];
    #pragma unroll
    for (int i = 0; i < 4; i++)
        #pragma unroll
        for (int j = 0; j < 4; j++)
            #pragma unroll
            for (int e = 0; e < 4; e++) acc[i][j][e] = 0.f;

    uint32_t smBase = smem_u32(sm);
    int nch = K >> 5;

    auto stage = [&](int c, int s){
        uint32_t bs = smBase + s * 32768;
        int k0 = c * 32;
        #pragma unroll
        for (int j = 0; j < 2; j++) {
            int id = tid + j * 256;
            int r = id >> 2, cc = id & 3;
            uint32_t d = bs + (uint32_t)(r * 64 + ((cc ^ ((r >> 1) & 3)) << 4));
            CP16(d, Ah + (long long)(m0 + r) * lda + k0 + cc * 8);
            uint32_t db = bs + 16384 + (uint32_t)(r * 64 + ((cc ^ ((r >> 1) & 3)) << 4));
            CP16(db, Bh + (long long)(n0 + r) * ldb + k0 + cc * 8);
            CP16(db + 8192, Bl + (long long)(n0 + r) * ldb + k0 + cc * 8);
        }
        CPCOMMIT();
    };
    stage(0, 0);
    if (nch > 1) stage(1, 1); else CPCOMMIT();

    uint32_t aRowB = (uint32_t)(wm0 + (lane & 15)) * 64;
    uint32_t aXor  = ((uint32_t)(lane & 15) >> 1) & 3;
    uint32_t aG    = (uint32_t)(lane >> 4);
    uint32_t bRowB = (uint32_t)(wn0 + ((lane >> 4) << 3) + (lane & 7)) * 64;
    uint32_t bXor  = (((uint32_t)lane & 7) >> 1) & 3;
    uint32_t bG    = (uint32_t)((lane >> 3) & 1);

    for (int c = 0; c < nch; c++) {
        CPWAIT1();
        __syncthreads();
        uint32_t base = smBase + (uint32_t)((c % 3) * 32768);
        #pragma unroll
        for (int ks = 0; ks < 2; ks++) {
            uint32_t bh[8], bl[8];
            #pragma unroll
            for (int ntp = 0; ntp < 2; ntp++) {
                uint32_t ga = (uint32_t)(ks * 2) + bG;
                uint32_t off = bRowB + (uint32_t)(ntp * 1024) + ((ga ^ bXor) << 4);
                ldsm4(bh[ntp*4+0], bh[ntp*4+1], bh[ntp*4+2], bh[ntp*4+3], base + 16384 + off);
                ldsm4(bl[ntp*4+0], bl[ntp*4+1], bl[ntp*4+2], bl[ntp*4+3], base + 24576 + off);
            }
            #pragma unroll
            for (int mt = 0; mt < 4; mt++) {
                uint32_t ga = (uint32_t)(ks * 2) + aG;
                uint32_t off = aRowB + (uint32_t)(mt * 1024) + ((ga ^ aXor) << 4);
                uint32_t ah[4];
                ldsm4(ah[0], ah[1], ah[2], ah[3], base + off);
                #pragma unroll
                for (int nt = 0; nt < 4; nt++) {
                    const uint32_t* ph = &bh[(nt >> 1) * 4 + (nt & 1) * 2];
                    const uint32_t* pl = &bl[(nt >> 1) * 4 + (nt & 1) * 2];
                    mma16816(acc[mt][nt], ah, ph);
                    mma16816(acc[mt][nt], ah, pl);
                }
            }
        }
        if (c + 2 < nch) stage(c + 2, (c + 2) % 3); else CPCOMMIT();
    }
    #pragma unroll
    for (int nt = 0; nt < 4; nt++) {
        int cc = n0 + wn0 + nt * 8 + (lane & 3) * 2;
        float b0 = bias[cc], b1 = bias[cc + 1];
        #pragma unroll
        for (int mt = 0; mt < 4; mt++) {
            int r = m0 + wm0 + mt * 16 + (lane >> 2);
            *(float2*)(Cf + (long long)r * ldc + cc) =
                make_float2(acc[mt][nt][0] + b0, acc[mt][nt][1] + b1);
            *(float2*)(Cf + (long long)(r + 8) * ldc + cc) =
                make_float2(acc[mt][nt][2] + b0, acc[mt][nt][3] + b1);
        }
    }
}

// ====================== BK=64 grid-mapped GEMM (main ops) ===================
// BTRANS: B [K,N] (NN, trans); else [N,K] (NT). OUT: 0 fp32, 2 fp16.
// rpart (optional): 8 per-ktile partial rowsums; epilogue divides by their sum.
#define G64_SMEM (3*32768)

template<bool BTRANS, int OUT, bool RELU>
__global__ __launch_bounds__(256,2) void gemm64(
    const __half* __restrict__ Ah_, const __half* __restrict__ Bh_,
    const float* __restrict__ bias, const float* __restrict__ rpart,
    float* __restrict__ Cf, __half* __restrict__ Ch,
    int K, int lda, int ldb, int ldc,
    long long sA, long long sB, long long sC)
{
    extern __shared__ char sm[];
    int tid = threadIdx.x, lane = tid & 31, wid = tid >> 5;
    int z = blockIdx.z;
    const __half* Ah = Ah_ + (long long)z * sA;
    const __half* Bh = Bh_ + (long long)z * sB;
    int m0 = blockIdx.y * 128, n0 = blockIdx.x * 128;
    int wm0 = (wid >> 2) * 64, wn0 = (wid & 3) * 32;

    float acc[4][4][4];
    #pragma unroll
    for (int i = 0; i < 4; i++)
        #pragma unroll
        for (int j = 0; j < 4; j++)
            #pragma unroll
            for (int e = 0; e < 4; e++) acc[i][j][e] = 0.f;

    uint32_t smBase = smem_u32(sm);
    int nch = K >> 6;

    auto stage = [&](int c, int s){
        uint32_t bs = smBase + s * 32768;
        int k0 = c * 64;
        #pragma unroll
        for (int j = 0; j < 4; j++) {
            int id = tid + j * 256;
            int r = id >> 3, cc = id & 7;
            uint32_t off = (uint32_t)(r * 128 + ((cc ^ (r & 7)) << 4));
            CP16(bs + off, Ah + (long long)(m0 + r) * lda + k0 + cc * 8);
        }
        if (!BTRANS) {
            #pragma unroll
            for (int j = 0; j < 4; j++) {
                int id = tid + j * 256;
                int r = id >> 3, cc = id & 7;
                uint32_t off = (uint32_t)(r * 128 + ((cc ^ (r & 7)) << 4));
                CP16(bs + 16384 + off, Bh + (long long)(n0 + r) * ldb + k0 + cc * 8);
            }
        } else {
            #pragma unroll
            for (int j = 0; j < 4; j++) {
                int id = tid + j * 256;
                int k = id >> 4, cc = id & 15;
                uint32_t off = (uint32_t)(k * 256 + ((cc ^ (k & 7)) << 4));
                CP16(bs + 16384 + off, Bh + (long long)(k0 + k) * ldb + n0 + cc * 8);
            }
        }
        CPCOMMIT();
    };
    stage(0, 0);
    if (nch > 1) stage(1, 1); else CPCOMMIT();

    uint32_t aRow = (uint32_t)(wm0 + (lane & 15));
    uint32_t bRowNT = (uint32_t)(wn0 + ((lane >> 4) << 3) + (lane & 7));
    uint32_t btRow = ((((uint32_t)lane >> 3) & 1) * 8 + ((uint32_t)lane & 7)) * 256;
    uint32_t btNc  = ((uint32_t)wn0 >> 3) + ((uint32_t)lane >> 4);
    uint32_t btXk  = (uint32_t)lane & 7;

    for (int c = 0; c < nch; c++) {
        CPWAIT1();
        __syncthreads();
        uint32_t base = smBase + (uint32_t)((c % 3) * 32768);
        #pragma unroll
        for (int ks = 0; ks < 4; ks++) {
            uint32_t bh[8];
            if (!BTRANS) {
                #pragma unroll
                for (int ntp = 0; ntp < 2; ntp++) {
                    uint32_t row = bRowNT + (uint32_t)(ntp * 16);
                    uint32_t g = (uint32_t)(ks * 2) + (uint32_t)((lane >> 3) & 1);
                    uint32_t off = row * 128 + ((g ^ (row & 7)) << 4);
                    ldsm4(bh[ntp*4+0], bh[ntp*4+1], bh[ntp*4+2], bh[ntp*4+3],
                          base + 16384 + off);
                }
            } else {
                #pragma unroll
                for (int ntp = 0; ntp < 2; ntp++) {
                    uint32_t off = btRow + (uint32_t)(ks * 4096)
                                 + (((btNc + (uint32_t)(ntp * 2)) ^ btXk) << 4);
                    ldsm4t(bh[ntp*4+0], bh[ntp*4+1], bh[ntp*4+2], bh[ntp*4+3],
                           base + 16384 + off);
                }
            }
            #pragma unroll
            for (int mt = 0; mt < 4; mt++) {
                uint32_t row = aRow + (uint32_t)(mt * 16);
                uint32_t g = (uint32_t)(ks * 2) + (uint32_t)(lane >> 4);
                uint32_t off = row * 128 + ((g ^ (row & 7)) << 4);
                uint32_t ah[4];
                ldsm4(ah[0], ah[1], ah[2], ah[3], base + off);
                #pragma unroll
                for (int nt = 0; nt < 4; nt++)
                    mma16816(acc[mt][nt], ah, &bh[(nt >> 1) * 4 + (nt & 1) * 2]);
            }
        }
        if (c + 2 < nch) stage(c + 2, (c + 2) % 3); else CPCOMMIT();
    }

    float rd0[4], rd1[4];
    if (rpart) {
        #pragma unroll
        for (int mt = 0; mt < 4; mt++) {
            int r = m0 + wm0 + mt * 16 + (lane >> 2);
            long long rb = (long long)z * 1024 + r;
            float s0 = 0.f, s1 = 0.f;
            #pragma unroll
            for (int kt = 0; kt < 8; kt++) {
                s0 += rpart[kt * ROWS + rb];
                s1 += rpart[kt * ROWS + rb + 8];
            }
            rd0[mt] = 1.f / s0;
            rd1[mt] = 1.f / s1;
        }
    }

    #pragma unroll
    for (int nt = 0; nt < 4; nt++) {
        int cc = n0 + wn0 + nt * 8 + (lane & 3) * 2;
        float b0 = 0.f, b1 = 0.f;
        if (bias) { b0 = bias[cc]; b1 = bias[cc + 1]; }
        #pragma unroll
        for (int mt = 0; mt < 4; mt++) {
            int r = m0 + wm0 + mt * 16 + (lane >> 2);
            float v0 = acc[mt][nt][0] + b0;
            float v1 = acc[mt][nt][1] + b1;
            float v2 = acc[mt][nt][2] + b0;
            float v3 = acc[mt][nt][3] + b1;
            if (rpart) { v0 *= rd0[mt]; v1 *= rd0[mt]; v2 *= rd1[mt]; v3 *= rd1[mt]; }
            if (RELU) { v0 = fmaxf(v0,0.f); v1 = fmaxf(v1,0.f); v2 = fmaxf(v2,0.f); v3 = fmaxf(v3,0.f); }
            if (OUT == 0) {
                float* p = Cf + (long long)z * sC;
                *(float2*)(p + (long long)r * ldc + cc)       = make_float2(v0, v1);
                *(float2*)(p + (long long)(r + 8) * ldc + cc) = make_float2(v2, v3);
            } else {
                __half* ph = Ch + (long long)z * sC;
                *(__half2*)(ph + (long long)r * ldc + cc) =
                    __halves2half2(__float2half_rn(v0), __float2half_rn(v1));
                *(__half2*)(ph + (long long)(r + 8) * ldc + cc) =
                    __halves2half2(__float2half_rn(v2), __float2half_rn(v3));
            }
        }
    }
}

// ====================== fused attention pass A: 1/sumexp ====================
#define SE_SMEM (3*16384)

__global__ __launch_bounds__(256,3) void sumexp_k(
    const __half* __restrict__ qk, float* __restrict__ sinv)
{
    extern __shared__ char sm[];
    int tid = threadIdx.x, lane = tid & 31, wid = tid >> 5;
    int wm0 = wid * 16;
    int z = blockIdx.y, b = z >> 3, h = z & 7;
    int m0 = blockIdx.x * 128;
    const __half* qb = qk + (long long)b * SS * 1024 + h * 64;
    const __half* kb = qb + 512;
    uint32_t smBase = smem_u32(sm);

    #pragma unroll
    for (int j = 0; j < 4; j++) {
        int id = tid + j * 256;
        int r = id >> 3, cc = id & 7;
        uint32_t off = (uint32_t)(r * 128 + ((cc ^ (r & 7)) << 4));
        CP16(smBase + off, qb + (long long)(m0 + r) * 1024 + cc * 8);
    }
    auto stageK = [&](int kt, int s){
        uint32_t bs = smBase + 16384 + s * 16384;
        int n0 = kt * 128;
        #pragma unroll
        for (int j = 0; j < 4; j++) {
            int id = tid + j * 256;
            int r = id >> 3, cc = id & 7;
            uint32_t off = (uint32_t)(r * 128 + ((cc ^ (r & 7)) << 4));
            CP16(bs + off, kb + (long long)(n0 + r) * 1024 + cc * 8);
        }
        CPCOMMIT();
    };
    stageK(0, 0);
    stageK(1, 1);

    uint32_t aRow = (uint32_t)(wm0 + (lane & 15));
    uint32_t bRow0 = (uint32_t)(((lane >> 4) << 3) + (lane & 7));
    float sum0 = 0.f, sum1 = 0.f;

    for (int kt = 0; kt < 8; kt++) {
        CPWAIT1();
        __syncthreads();
        uint32_t kbase = smBase + 16384 + (uint32_t)((kt & 1) * 16384);
        uint32_t hacc[16][2];
        #pragma unroll
        for (int i = 0; i < 16; i++) { hacc[i][0] = 0u; hacc[i][1] = 0u; }
        #pragma unroll
        for (int ks = 0; ks < 4; ks++) {
            uint32_t ag = (uint32_t)(ks * 2) + (uint32_t)(lane >> 4);
            uint32_t ah[4];
            ldsm4(ah[0], ah[1], ah[2], ah[3],
                  smBase + aRow * 128 + ((ag ^ (aRow & 7)) << 4));
            #pragma unroll
            for (int ntp = 0; ntp < 8; ntp++) {
                uint32_t row = bRow0 + (uint32_t)(ntp * 16);
                uint32_t bg = (uint32_t)(ks * 2) + (uint32_t)((lane >> 3) & 1);
                uint32_t r4[4];
                ldsm4(r4[0], r4[1], r4[2], r4[3],
                      kbase + row * 128 + ((bg ^ (row & 7)) << 4));
                mma16816h(hacc[ntp*2],     ah, &r4[0]);
                mma16816h(hacc[ntp*2 + 1], ah, &r4[2]);
            }
        }
        #pragma unroll
        for (int nt = 0; nt < 16; nt++) {
            float2 f0 = __half22float2(*reinterpret_cast<__half2*>(&hacc[nt][0]));
            float2 f1 = __half22float2(*reinterpret_cast<__half2*>(&hacc[nt][1]));
            sum0 += __expf(f0.x * 0.125f) + __expf(f0.y * 0.125f);
            sum1 += __expf(f1.x * 0.125f) + __expf(f1.y * 0.125f);
        }
        __syncthreads();
        if (kt + 2 < 8) stageK(kt + 2, kt & 1); else CPCOMMIT();
    }
    sum0 += __shfl_xor_sync(0xffffffffu, sum0, 1);
    sum0 += __shfl_xor_sync(0xffffffffu, sum0, 2);
    sum1 += __shfl_xor_sync(0xffffffffu, sum1, 1);
    sum1 += __shfl_xor_sync(0xffffffffu, sum1, 2);
    if ((lane & 3) == 0) {
        int r = m0 + wm0 + (lane >> 2);
        sinv[(long long)z * SS + r]     = 1.f / sum0;
        sinv[(long long)z * SS + r + 8] = 1.f / sum1;
    }
}

// ====================== fused attention pass B: w~ + partial rowsums ========
#define FW_SMEM (2*32768)

__global__ __launch_bounds__(256,2) void fuse_w_k(
    const __half* __restrict__ qk, const float* __restrict__ sinv,
    const __half* __restrict__ dbias, __half* __restrict__ wh,
    float* __restrict__ rpart)
{
    extern __shared__ char sm[];
    int tid = threadIdx.x, lane = tid & 31, wid = tid >> 5;
    int wm0 = wid * 16;
    int b = blockIdx.z, qt = blockIdx.y, kt = blockIdx.x;
    int m0 = qt * 128, n0 = kt * 128;
    const __half* base_q = qk + (long long)b * SS * 1024;
    uint32_t smBase = smem_u32(sm);

    auto stageH = [&](int h, int s){
        uint32_t bs = smBase + s * 32768;
        const __half* qb = base_q + h * 64;
        const __half* kb = qb + 512;
        #pragma unroll
        for (int j = 0; j < 8; j++) {
            int id = tid + j * 256;
            int r = (id & 1023) >> 3, cc = id & 7;
            uint32_t off = (uint32_t)(r * 128 + ((cc ^ (r & 7)) << 4));
            if (id < 1024) CP16(bs + off, qb + (long long)(m0 + r) * 1024 + cc * 8);
            else           CP16(bs + 16384 + off, kb + (long long)(n0 + r) * 1024 + cc * 8);
        }
        CPCOMMIT();
    };
    stageH(0, 0);
    stageH(1, 1);

    uint32_t aRow = (uint32_t)(wm0 + (lane & 15));
    uint32_t bRow0 = (uint32_t)(((lane >> 4) << 3) + (lane & 7));
    int r0 = wm0 + (lane >> 2);
    uint32_t wacc[16][2];
    #pragma unroll
    for (int i = 0; i < 16; i++) { wacc[i][0] = 0u; wacc[i][1] = 0u; }

    for (int h = 0; h < 8; h++) {
        CPWAIT1();
        __syncthreads();
        uint32_t qbase = smBase + (uint32_t)((h & 1) * 32768);
        uint32_t kbase = qbase + 16384;
        uint32_t hacc[16][2];
        #pragma unroll
        for (int i = 0; i < 16; i++) { hacc[i][0] = 0u; hacc[i][1] = 0u; }
        #pragma unroll
        for (int ks = 0; ks < 4; ks++) {
            uint32_t ag = (uint32_t)(ks * 2) + (uint32_t)(lane >> 4);
            uint32_t ah[4];
            ldsm4(ah[0], ah[1], ah[2], ah[3],
                  qbase + aRow * 128 + ((ag ^ (aRow & 7)) << 4));
            #pragma unroll
            for (int ntp = 0; ntp < 8; ntp++) {
                uint32_t row = bRow0 + (uint32_t)(ntp * 16);
                uint32_t bg = (uint32_t)(ks * 2) + (uint32_t)((lane >> 3) & 1);
                uint32_t r4[4];
                ldsm4(r4[0], r4[1], r4[2], r4[3],
                      kbase + row * 128 + ((bg ^ (row & 7)) << 4));
                mma16816h(hacc[ntp*2],     ah, &r4[0]);
                mma16816h(hacc[ntp*2 + 1], ah, &r4[2]);
            }
        }
        long long sbase = (long long)(b * 8 + h) * SS + m0;
        float is0 = sinv[sbase + r0];
        float is1 = sinv[sbase + r0 + 8];
        #pragma unroll
        for (int nt = 0; nt < 16; nt++) {
            float2 f0 = __half22float2(*reinterpret_cast<__half2*>(&hacc[nt][0]));
            float2 f1 = __half22float2(*reinterpret_cast<__half2*>(&hacc[nt][1]));
            __half2 t0 = __floats2half2_rn(__expf(f0.x * 0.125f) * is0,
                                           __expf(f0.y * 0.125f) * is0);
            __half2 t1 = __floats2half2_rn(__expf(f1.x * 0.125f) * is1,
                                           __expf(f1.y * 0.125f) * is1);
            *reinterpret_cast<__half2*>(&wacc[nt][0]) =
                __hadd2(*reinterpret_cast<__half2*>(&wacc[nt][0]), t0);
            *reinterpret_cast<__half2*>(&wacc[nt][1]) =
                __hadd2(*reinterpret_cast<__half2*>(&wacc[nt][1]), t1);
        }
        __syncthreads();
        if (h + 2 < 8) stageH(h + 2, h & 1); else CPCOMMIT();
    }

    long long row0 = (long long)(b * SS + m0 + r0);
    const __half* db0 = dbias + row0 * SS;
    __half* wp0 = wh + row0 * SS;
    int ccb = n0 + (lane & 3) * 2;
    float ps0 = 0.f, ps1 = 0.f;
    #pragma unroll
    for (int nt = 0; nt < 16; nt++) {
        int col = ccb + nt * 8;
        __half2 d0 = *(const __half2*)(db0 + col);
        __half2 d1 = *(const __half2*)(db0 + 8 * SS + col);
        __half2 v0 = __hmul2(*reinterpret_cast<__half2*>(&wacc[nt][0]), d0);
        __half2 v1 = __hmul2(*reinterpret_cast<__half2*>(&wacc[nt][1]), d1);
        *(__half2*)(wp0 + col) = v0;
        *(__half2*)(wp0 + 8 * SS + col) = v1;
        float2 f0 = __half22float2(v0), f1 = __half22float2(v1);
        ps0 += f0.x + f0.y;
        ps1 += f1.x + f1.y;
    }
    ps0 += __shfl_xor_sync(0xffffffffu, ps0, 1);
    ps0 += __shfl_xor_sync(0xffffffffu, ps0, 2);
    ps1 += __shfl_xor_sync(0xffffffffu, ps1, 1);
    ps1 += __shfl_xor_sync(0xffffffffu, ps1, 2);
    if ((lane & 3) == 0) {
        rpart[kt * ROWS + row0]     = ps0;
        rpart[kt * ROWS + row0 + 8] = ps1;
    }
}

// ---------------- fp32 -> fp16 converters (8 elems/thread) ------------------
__global__ void split_k(const float* __restrict__ in, __half* __restrict__ h,
                        __half* __restrict__ l, int n8) {
    int i = blockIdx.x * 256 + threadIdx.x;
    if (i >= n8) return;
    long long base = (long long)i * 8;
    float4 a = *(const float4*)(in + base);
    float4 b = *(const float4*)(in + base + 4);
    float va[8] = {a.x, a.y, a.z, a.w, b.x, b.y, b.z, b.w};
    uint4 hp, lp;
    uint32_t* hw = reinterpret_cast<uint32_t*>(&hp);
    uint32_t* lw = reinterpret_cast<uint32_t*>(&lp);
    #pragma unroll
    for (int j = 0; j < 4; j++) {
        __half h0 = __float2half_rn(va[j*2]), h1 = __float2half_rn(va[j*2+1]);
        __half2 hh = __halves2half2(h0, h1);
        __half2 ll = __halves2half2(__float2half_rn(va[j*2]   - __half2float(h0)),
                                    __float2half_rn(va[j*2+1] - __half2float(h1)));
        hw[j] = *reinterpret_cast<uint32_t*>(&hh);
        lw[j] = *reinterpret_cast<uint32_t*>(&ll);
    }
    *(uint4*)(h + base) = hp;
    *(uint4*)(l + base) = lp;
}
__global__ void cvt_k(const float* __restrict__ in, __half* __restrict__ h, int n8) {
    int i = blockIdx.x * 256 + threadIdx.x;
    if (i >= n8) return;
    long long base = (long long)i * 8;
    float4 a = *(const float4*)(in + base);
    float4 b = *(const float4*)(in + base + 4);
    uint4 hp;
    uint32_t* hw = reinterpret_cast<uint32_t*>(&hp);
    __half2 h0 = __floats2half2_rn(a.x, a.y);
    __half2 h1 = __floats2half2_rn(a.z, a.w);
    __half2 h2 = __floats2half2_rn(b.x, b.y);
    __half2 h3 = __floats2half2_rn(b.z, b.w);
    hw[0] = *reinterpret_cast<uint32_t*>(&h0);
    hw[1] = *reinterpret_cast<uint32_t*>(&h1);
    hw[2] = *reinterpret_cast<uint32_t*>(&h2);
    hw[3] = *reinterpret_cast<uint32_t*>(&h3);
    *(uint4*)(h + base) = hp;
}

// ---------------- BatchNorm (training-mode batch stats), deterministic -----
__global__ void bn_part_k(const float* __restrict__ x, float* __restrict__ part) {
    int e = threadIdx.x;
    int blk = blockIdx.x;
    float s = 0.f, sq = 0.f;
    int r0 = blk * 128;
    for (int r = r0; r < r0 + 128; r++) {
        float v = x[(long long)r * EE + e];
        s += v; sq += v * v;
    }
    part[blk * EE + e] = s;
    part[(64 + blk) * EE + e] = sq;
}

__global__ void bn_final_k(const float* __restrict__ part, float* __restrict__ stats) {
    int e = blockIdx.x * blockDim.x + threadIdx.x;
    float s = 0.f, sq = 0.f;
    for (int i = 0; i < 64; i++) {
        s  += part[i * EE + e];
        sq += part[(64 + i) * EE + e];
    }
    float mu = s / (float)ROWS;
    stats[e] = mu;
    stats[EE + e] = sq / (float)ROWS - mu * mu;
}

__global__ void bn_apply_pe_k(float* __restrict__ x, const float* __restrict__ stats,
                              const float* __restrict__ g, const float* __restrict__ b,
                              __half* __restrict__ xh) {
    long long idx = (long long)blockIdx.x * blockDim.x + threadIdx.x;
    int e = (int)(idx & (EE - 1));
    long long r = idx >> 9;
    int s = (int)(r & (SS - 1));
    float mu = stats[e], var = stats[EE + e];
    int j = e >> 1;
    float dt = expf((float)(2 * j) * (-9.210340371976184f / (float)EE));
    float ang = (float)s * dt;
    float pe = (e & 1) ? cosf(ang) : sinf(ang);
    float v = (x[idx] - mu) * rsqrtf(var + EPS) * g[e] + b[e] + pe;
    x[idx] = v;
    xh[idx] = __float2half_rn(v);
}

// ---------------- distance bias (warp per row, fp16 out) --------------------
__global__ void dist_bias_k(const float* __restrict__ d, const float* __restrict__ scale_p,
                            __half* __restrict__ bias) {
    int row = blockIdx.x * 8 + (threadIdx.x >> 5);
    int lane = threadIdx.x & 31;
    const float* dp = d + (long long)row * SS + lane * 4;
    float4 v[8];
    float mx = -1e30f;
    #pragma unroll
    for (int i = 0; i < 8; i++) {
        v[i] = *(const float4*)(dp + i * 128);
        mx = fmaxf(mx, fmaxf(fmaxf(v[i].x, v[i].y), fmaxf(v[i].z, v[i].w)));
    }
    mx = wrmax(mx);
    float inv_dmax = 1.f / mx;
    float sc = scale_p[0];
    __half* bp = bias + (long long)row * SS + lane * 4;
    #pragma unroll
    for (int i = 0; i < 8; i++) {
        __half2 h0 = __halves2half2(__float2half_rn(expf(sc * (1.f - v[i].x * inv_dmax))),
                                    __float2half_rn(expf(sc * (1.f - v[i].y * inv_dmax))));
        __half2 h1 = __halves2half2(__float2half_rn(expf(sc * (1.f - v[i].z * inv_dmax))),
                                    __float2half_rn(expf(sc * (1.f - v[i].w * inv_dmax))));
        uint2 pk; pk.x = *reinterpret_cast<uint32_t*>(&h0); pk.y = *reinterpret_cast<uint32_t*>(&h1);
        *(uint2*)(bp + i * 128) = pk;
    }
}

// ---------------- fused residual + LayerNorm (warp per row) -----------------
template<bool SPLIT>
__global__ void add_ln_k(const float* __restrict__ x, const float* __restrict__ r,
                         const float* __restrict__ g, const float* __restrict__ b,
                         float* __restrict__ out, __half* __restrict__ oh) {
    int row = blockIdx.x * 8 + (threadIdx.x >> 5);
    int lane = threadIdx.x & 31;
    long long base = (long long)row * EE + lane * 4;
    float4 v[4];
    float s = 0.f, sq = 0.f;
    #pragma unroll
    for (int i = 0; i < 4; i++) {
        float4 a = *(const float4*)(x + base + i * 128);
        float4 rr = *(const float4*)(r + base + i * 128);
        a.x += rr.x; a.y += rr.y; a.z += rr.z; a.w += rr.w;
        v[i] = a;
        s += a.x + a.y + a.z + a.w;
        sq += a.x*a.x + a.y*a.y + a.z*a.z + a.w*a.w;
    }
    float mean = wrsum(s) * (1.f / (float)EE);
    float var = wrsum(sq) * (1.f / (float)EE) - mean * mean;
    float inv = rsqrtf(var + EPS);
    #pragma unroll
    for (int i = 0; i < 4; i++) {
        float4 gg = *(const float4*)(g + lane * 4 + i * 128);
        float4 bb = *(const float4*)(b + lane * 4 + i * 128);
        float4 o;
        o.x = (v[i].x - mean) * inv * gg.x + bb.x;
        o.y = (v[i].y - mean) * inv * gg.y + bb.y;
        o.z = (v[i].z - mean) * inv * gg.z + bb.z;
        o.w = (v[i].w - mean) * inv * gg.w + bb.w;
        *(float4*)(out + base + i * 128) = o;
        if (SPLIT) {
            __half2 h0 = __halves2half2(__float2half_rn(o.x), __float2half_rn(o.y));
            __half2 h1 = __halves2half2(__float2half_rn(o.z), __float2half_rn(o.w));
            uint2 pk; pk.x = *reinterpret_cast<uint32_t*>(&h0); pk.y = *reinterpret_cast<uint32_t*>(&h1);
            *(uint2*)(oh + base + i * 128) = pk;
        }
    }
}

// ---------------- launch -----------------------------------------------------
extern "C" void kernel_launch(void* const* d_in, const int* in_sizes, int n_in,
                              void* d_out, int out_size) {
    (void)in_sizes; (void)n_in; (void)out_size;
    const float* src        = (const float*)d_in[0];
    const float* distances  = (const float*)d_in[1];
    const float* proj_w     = (const float*)d_in[2];
    const float* proj_b     = (const float*)d_in[3];
    const float* bn_g       = (const float*)d_in[4];
    const float* bn_b       = (const float*)d_in[5];
    const float* in_proj_w  = (const float*)d_in[6];
    const float* in_proj_b  = (const float*)d_in[7];
    const float* dist_scale = (const float*)d_in[8];
    const float* lin1_w     = (const float*)d_in[9];
    const float* lin1_b     = (const float*)d_in[10];
    const float* lin2_w     = (const float*)d_in[11];
    const float* lin2_b     = (const float*)d_in[12];
    const float* n1_g       = (const float*)d_in[13];
    const float* n1_b       = (const float*)d_in[14];
    const float* n2_g       = (const float*)d_in[15];
    const float* n2_b       = (const float*)d_in[16];
    float* out = (float*)d_out;

    float *x, *attn, *part, *stats, *sinv, *rpart;
    __half *dbias, *srch, *xh, *qkh, *wh, *ffh;
    __half *pwh, *pwl, *iph, *l1h, *l2h;
    cudaGetSymbolAddress((void**)&x,     g_x);
    cudaGetSymbolAddress((void**)&dbias, g_dbias);
    cudaGetSymbolAddress((void**)&attn,  g_attn);
    cudaGetSymbolAddress((void**)&part,  g_part);
    cudaGetSymbolAddress((void**)&stats, g_stats);
    cudaGetSymbolAddress((void**)&sinv,  g_sinv);
    cudaGetSymbolAddress((void**)&rpart, g_rpart);
    cudaGetSymbolAddress((void**)&srch,  g_srch);
    cudaGetSymbolAddress((void**)&xh,    g_xh);
    cudaGetSymbolAddress((void**)&qkh,   g_qkh);
    cudaGetSymbolAddress((void**)&wh,    g_wh);
    cudaGetSymbolAddress((void**)&ffh,   g_ffh);
    cudaGetSymbolAddress((void**)&pwh,   g_pwh);  cudaGetSymbolAddress((void**)&pwl,  g_pwl);
    cudaGetSymbolAddress((void**)&iph,   g_iph);
    cudaGetSymbolAddress((void**)&l1h,   g_l1h);
    cudaGetSymbolAddress((void**)&l2h,   g_l2h);

    cudaFuncSetAttribute(gemm_proj, cudaFuncAttributeMaxDynamicSharedMemorySize, GEMM_SMEM);
    cudaFuncSetAttribute(gemm64<false,2,false>, cudaFuncAttributeMaxDynamicSharedMemorySize, G64_SMEM);
    cudaFuncSetAttribute(gemm64<false,2,true>,  cudaFuncAttributeMaxDynamicSharedMemorySize, G64_SMEM);
    cudaFuncSetAttribute(gemm64<true,0,false>,  cudaFuncAttributeMaxDynamicSharedMemorySize, G64_SMEM);
    cudaFuncSetAttribute(gemm64<false,0,false>, cudaFuncAttributeMaxDynamicSharedMemorySize, G64_SMEM);
    cudaFuncSetAttribute(sumexp_k, cudaFuncAttributeMaxDynamicSharedMemorySize, SE_SMEM);
    cudaFuncSetAttribute(fuse_w_k, cudaFuncAttributeMaxDynamicSharedMemorySize, FW_SMEM);

    dim3 blk(256);
    const long long SE  = (long long)SS * EE;
    const long long SS2 = (long long)SS * SS;

    // 0) one-time conversions
    cvt_k<<<(ROWS*IN_F/8+255)/256, 256>>>(src, srch, ROWS*IN_F/8);
    split_k<<<(EE*IN_F/8+255)/256, 256>>>(proj_w, pwh, pwl, EE*IN_F/8);
    cvt_k<<<(1024*EE/8+255)/256, 256>>>(in_proj_w, iph, 1024*EE/8);
    cvt_k<<<(FF_DIM*EE/8+255)/256, 256>>>(lin1_w, l1h, FF_DIM*EE/8);
    cvt_k<<<(EE*FF_DIM/8+255)/256, 256>>>(lin2_w, l2h, EE*FF_DIM/8);

    // 1) input projection -> g_x (fp32), 2-pass (src single, weight split)
    gemm_proj<<<dim3(EE/128, ROWS/128, 1), blk, GEMM_SMEM>>>(
        srch, pwh, pwl, proj_b, x, IN_F, IN_F, IN_F, EE);

    // 2) BatchNorm + PE (+fp16 mirror)
    bn_part_k<<<64, 512>>>(x, part);
    bn_final_k<<<2, 256>>>(part, stats);
    bn_apply_pe_k<<<(ROWS*EE)/256, 256>>>(x, stats, bn_g, bn_b, xh);

    // 3) distance bias
    dist_bias_k<<<BB*SS/8, 256>>>(distances, dist_scale, dbias);

    // 4) layers
    for (int l = 0; l < NL; l++) {
        // qk projection -> fp16
        gemm64<false,2,false><<<dim3(1024/128, ROWS/128, 1), blk, G64_SMEM>>>(
            xh, iph, in_proj_b, nullptr, nullptr, qkh,
            EE, EE, EE, 1024, 0, 0, 0);

        // fused attention weights (+partial rowsums)
        sumexp_k<<<dim3(8, BB*HH), blk, SE_SMEM>>>(qkh, sinv);
        fuse_w_k<<<dim3(8, 8, BB), blk, FW_SMEM>>>(qkh, sinv, dbias, wh, rpart);

        // attn_out = (w~ @ x) / rowsum -> fp32
        gemm64<true,0,false><<<dim3(EE/128, SS/128, BB), blk, G64_SMEM>>>(
            wh, xh, nullptr, rpart, attn, nullptr,
            SS, SS, EE, EE, SS2, SE, SE);

        // x = LN(x + attn_out)
        add_ln_k<true><<<ROWS/8, 256>>>(x, attn, n1_g, n1_b, x, xh);

        // FFN
        gemm64<false,2,true><<<dim3(FF_DIM/128, ROWS/128, 1), blk, G64_SMEM>>>(
            xh, l1h, lin1_b, nullptr, nullptr, ffh,
            EE, EE, EE, FF_DIM, 0, 0, 0);
        gemm64<false,0,false><<<dim3(EE/128, ROWS/128, 1), blk, G64_SMEM>>>(
            ffh, l2h, lin2_b, nullptr, attn, nullptr,
            FF_DIM, FF_DIM, FF_DIM, EE, 0, 0, 0);

        // x = LN(x + ff); last layer -> d_out
        if (l == NL - 1)
            add_ln_k<false><<<ROWS/8, 256>>>(x, attn, n2_g, n2_b, out, nullptr);
        else
            add_ln_k<true><<<ROWS/8, 256>>>(x, attn, n2_g, n2_b, x, xh);
    }
}